// round 9
// baseline (speedup 1.0000x reference)
#include <cuda_runtime.h>
#include <cuda_bf16.h>
#include <cuda_fp16.h>

typedef unsigned long long ull;

// B=32, S=64, D=256, H=8, E=8, topk=2, F=1024, LATENT=64, HD=32
#define TOK      2048
#define DMODEL   256
#define NBIG     16384
#define FEXP     1024
#define NEXP     8
#define WLSPLIT  8
#define WLKC     (NBIG/WLSPLIT)   // 2048

// ---------------- scratch ----------------
__device__ float  g_y1 [TOK*DMODEL];
__device__ float  g_part[WLSPLIT*32*NBIG];
__device__ float  g_lat[TOK*DMODEL];
__device__ float  g_qkv[3*TOK*DMODEL];
__device__ float  g_ao [TOK*DMODEL];
__device__ float  g_x2 [TOK*DMODEL];
__device__ float  g_y2 [TOK*DMODEL];
__device__ float  g_topv[TOK*2];
__device__ int    g_cnt[NEXP];
__device__ int    g_list[NEXP*TOK];
__device__ float  g_h1 [NEXP*TOK*FEXP];
__device__ float  g_h2 [NEXP*TOK*FEXP];
__device__ float  g_eo [2*TOK*DMODEL];
__device__ __align__(16) __half g_w116[NEXP*DMODEL*FEXP];
__device__ __align__(16) __half g_ws16[NEXP*FEXP*FEXP];
__device__ __align__(16) __half g_w216[NEXP*FEXP*DMODEL];
__device__ __align__(16) __half g_wq16[DMODEL*DMODEL];
__device__ __align__(16) __half g_wk16[DMODEL*DMODEL];
__device__ __align__(16) __half g_wv16[DMODEL*DMODEL];
__device__ __align__(16) __half g_wo16[DMODEL*DMODEL];

// ---------------- helpers ----------------
__device__ __forceinline__ unsigned smem_u32(const void* p) {
    return (unsigned)__cvta_generic_to_shared(p);
}
__device__ __forceinline__ void ldm_x4(unsigned* r, unsigned addr) {
    asm volatile("ldmatrix.sync.aligned.m8n8.x4.shared.b16 {%0,%1,%2,%3}, [%4];"
        : "=r"(r[0]), "=r"(r[1]), "=r"(r[2]), "=r"(r[3]) : "r"(addr));
}
__device__ __forceinline__ void ldm_x4t(unsigned* r, unsigned addr) {
    asm volatile("ldmatrix.sync.aligned.m8n8.x4.trans.shared.b16 {%0,%1,%2,%3}, [%4];"
        : "=r"(r[0]), "=r"(r[1]), "=r"(r[2]), "=r"(r[3]) : "r"(addr));
}
__device__ __forceinline__ void ldm_x2t(unsigned* r, unsigned addr) {
    asm volatile("ldmatrix.sync.aligned.m8n8.x2.trans.shared.b16 {%0,%1}, [%2];"
        : "=r"(r[0]), "=r"(r[1]) : "r"(addr));
}
__device__ __forceinline__ void mma_bf16(float* c, const unsigned* a, const unsigned* b) {
    asm volatile("mma.sync.aligned.m16n8k16.row.col.f32.bf16.bf16.f32 "
        "{%0,%1,%2,%3}, {%4,%5,%6,%7}, {%8,%9}, {%0,%1,%2,%3};"
        : "+f"(c[0]), "+f"(c[1]), "+f"(c[2]), "+f"(c[3])
        : "r"(a[0]), "r"(a[1]), "r"(a[2]), "r"(a[3]), "r"(b[0]), "r"(b[1]));
}
__device__ __forceinline__ void mma_f16(float* c, const unsigned* a, const unsigned* b) {
    asm volatile("mma.sync.aligned.m16n8k16.row.col.f32.f16.f16.f32 "
        "{%0,%1,%2,%3}, {%4,%5,%6,%7}, {%8,%9}, {%0,%1,%2,%3};"
        : "+f"(c[0]), "+f"(c[1]), "+f"(c[2]), "+f"(c[3])
        : "r"(a[0]), "r"(a[1]), "r"(a[2]), "r"(a[3]), "r"(b[0]), "r"(b[1]));
}
// bf16 split (Wl kernel)
__device__ __forceinline__ void split_pair(float x, float y, unsigned& hi, unsigned& lo) {
    unsigned ux = __float_as_uint(x), uy = __float_as_uint(y);
    hi = __byte_perm(ux, uy, 0x7632);
    float lx = x - __uint_as_float(ux & 0xFFFF0000u);
    float ly = y - __uint_as_float(uy & 0xFFFF0000u);
    asm("cvt.rn.bf16x2.f32 %0, %1, %2;" : "=r"(lo) : "f"(ly), "f"(lx));
}
// fp16 pack / split
__device__ __forceinline__ unsigned pack_f16(float x, float y) {
    unsigned r;
    asm("cvt.rn.f16x2.f32 %0, %1, %2;" : "=r"(r) : "f"(y), "f"(x));
    return r;
}
__device__ __forceinline__ void split_pair_f16(float x, float y, unsigned& hi, unsigned& lo) {
    hi = pack_f16(x, y);
    __half2 h = *reinterpret_cast<__half2*>(&hi);
    float2 hf = __half22float2(h);
    lo = pack_f16(x - hf.x, y - hf.y);
}

// ================= hgemm: BM=128 BN=128 BK=32, fp16 weights, 2-pass A ==========
// mode 0: C[r]=A[r]@W+bias(+resid)   mode 1: A gathered via list>>1 -> C at e*TOK
// mode 2: A at e*TOK -> C at e*TOK (+relu)   mode 3: A at e*TOK -> C scattered (slot,tok)
// mode 5: fused QKV: z selects {A,W,bias}; C slice z*TOK*N
#define A128_STRIDE 40      // f16 elems (80 B)
#define B128_STRIDE 136     // f16 elems (272 B)
#define AH128 0
#define AL128 10240
#define BH128 20480
#define BUF128 29184        // AH + AL + BH(8704)
#define ROWP128 (2*BUF128)
#define SMEM128 (2*BUF128 + 1024 + 256)

extern "C" __global__ void __launch_bounds__(256)
hgemm(const float* __restrict__ A, const __half* __restrict__ W16,
      const float* __restrict__ bias, const float* __restrict__ resid,
      float* __restrict__ C, int M, int N, int K, int lda,
      const int* __restrict__ list, const int* __restrict__ cntp,
      int mode, int relu,
      const float* A2, const __half* Wk16, const __half* Wv16,
      const float* bk2, const float* bv3) {
    extern __shared__ char sm_raw[];
    char* sm = (char*)(((ull)sm_raw + 127) & ~127ULL);

    int z = blockIdx.z;
    int e = (mode >= 1 && mode <= 3) ? z : 0;
    const float* Asrc = A;
    const __half* Wsrc = W16;
    const float* bsrc = bias;
    if (mode == 5 && z > 0) {
        Asrc = A2;
        Wsrc = (z == 1) ? Wk16 : Wv16;
        bsrc = (z == 1) ? bk2 : bv3;
    }
    int rows = cntp ? cntp[e] : M;
    int m0 = blockIdx.y * 128;
    if (m0 >= rows) return;
    int n0 = blockIdx.x * 128;
    int tid = threadIdx.x;
    int lane = tid & 31, w = tid >> 5;
    int wm = w & 1, wn = w >> 1;

    const __half* We = Wsrc + (size_t)e * K * N;
    const float* be = bsrc + (size_t)e * N;

    const float** rowp = (const float**)(sm + ROWP128);
    if (tid < 128) {
        int r = m0 + tid;
        const float* p = nullptr;
        if (r < rows) {
            if (mode == 1)      p = Asrc + (size_t)(list[e*TOK + r] >> 1) * lda;
            else if (mode == 0 || mode == 5) p = Asrc + (size_t)r * lda;
            else                p = Asrc + ((size_t)e*TOK + r) * lda;
        }
        rowp[tid] = p;
    }
    __syncthreads();

    unsigned smbase = smem_u32(sm);
    int aq = lane >> 3, ar = lane & 7;
    unsigned a_base = smbase + AH128 +
        (unsigned)(((wm*64 + ar + 8*(aq & 1)) * A128_STRIDE + 8*(aq >> 1)) * 2);
    int bt = lane >> 3;
    int bkrow = (bt & 1)*8 + (lane & 7);
    int bnoff = (bt >> 1)*8;
    unsigned b_base = smbase + BH128 +
        (unsigned)((bkrow * B128_STRIDE + wn*32 + bnoff) * 2);

    float acc[4][4][4];
    #pragma unroll
    for (int i = 0; i < 4; i++)
        #pragma unroll
        for (int j = 0; j < 4; j++)
            #pragma unroll
            for (int q = 0; q < 4; q++) acc[i][j][q] = 0.f;

    int nch = K >> 5;
    float4 av[4];
    uint4 bpre[2];

    // ---- prologue: stage chunk 0 ----
    #pragma unroll
    for (int p = 0; p < 4; p++) {
        int s = tid + 256*p;
        const float* rp = rowp[s >> 3];
        av[p] = rp ? *(const float4*)(rp + (s & 7)*4) : make_float4(0.f,0.f,0.f,0.f);
    }
    #pragma unroll
    for (int p = 0; p < 2; p++) {
        int s = tid + 256*p;
        bpre[p] = *(const uint4*)(We + (size_t)(s >> 4)*N + n0 + (s & 15)*8);
    }
    {
        char* bb = sm;
        #pragma unroll
        for (int p = 0; p < 4; p++) {
            int s = tid + 256*p;
            int m = s >> 3, kq = s & 7;
            unsigned h0, l0, h1, l1;
            split_pair_f16(av[p].x, av[p].y, h0, l0);
            split_pair_f16(av[p].z, av[p].w, h1, l1);
            unsigned aoff = (unsigned)(m*(A128_STRIDE*2) + kq*8);
            *(uint2*)(bb + AH128 + aoff) = make_uint2(h0, h1);
            *(uint2*)(bb + AL128 + aoff) = make_uint2(l0, l1);
        }
        #pragma unroll
        for (int p = 0; p < 2; p++) {
            int s = tid + 256*p;
            *(uint4*)(bb + BH128 + (s >> 4)*272 + (s & 15)*16) = bpre[p];
        }
    }
    __syncthreads();

    for (int c = 0; c < nch; c++) {
        int buf = c & 1;
        bool has = (c + 1 < nch);
        if (has) {
            int kc = (c + 1) << 5;
            #pragma unroll
            for (int p = 0; p < 4; p++) {
                int s = tid + 256*p;
                const float* rp = rowp[s >> 3];
                av[p] = rp ? *(const float4*)(rp + kc + (s & 7)*4) : make_float4(0.f,0.f,0.f,0.f);
            }
            #pragma unroll
            for (int p = 0; p < 2; p++) {
                int s = tid + 256*p;
                bpre[p] = *(const uint4*)(We + (size_t)(kc + (s >> 4))*N + n0 + (s & 15)*8);
            }
        }
        // ---- compute on buf ----
        unsigned bufo = (unsigned)(buf * BUF128);
        #pragma unroll
        for (int ks = 0; ks < 2; ks++) {
            unsigned ah[4][4], al[4][4], bf[2][4];
            unsigned ab = a_base + bufo + ks*32;
            unsigned bb2 = b_base + bufo + ks*16*(B128_STRIDE*2);
            #pragma unroll
            for (int i = 0; i < 4; i++) {
                ldm_x4(ah[i], ab + i*16*(A128_STRIDE*2));
                ldm_x4(al[i], ab + i*16*(A128_STRIDE*2) + (AL128 - AH128));
            }
            #pragma unroll
            for (int jj = 0; jj < 2; jj++) ldm_x4t(bf[jj], bb2 + jj*32);
            #pragma unroll
            for (int i = 0; i < 4; i++)
                #pragma unroll
                for (int j = 0; j < 4; j++) {
                    mma_f16(acc[i][j], ah[i], &bf[j >> 1][(j & 1)*2]);
                    mma_f16(acc[i][j], al[i], &bf[j >> 1][(j & 1)*2]);
                }
        }
        if (has) {
            char* bb = sm + (buf ^ 1) * BUF128;
            #pragma unroll
            for (int p = 0; p < 4; p++) {
                int s = tid + 256*p;
                int m = s >> 3, kq = s & 7;
                unsigned h0, l0, h1, l1;
                split_pair_f16(av[p].x, av[p].y, h0, l0);
                split_pair_f16(av[p].z, av[p].w, h1, l1);
                unsigned aoff = (unsigned)(m*(A128_STRIDE*2) + kq*8);
                *(uint2*)(bb + AH128 + aoff) = make_uint2(h0, h1);
                *(uint2*)(bb + AL128 + aoff) = make_uint2(l0, l1);
            }
            #pragma unroll
            for (int p = 0; p < 2; p++) {
                int s = tid + 256*p;
                *(uint4*)(bb + BH128 + (s >> 4)*272 + (s & 15)*16) = bpre[p];
            }
        }
        __syncthreads();
    }

    // ---- epilogue ----
    #pragma unroll
    for (int i = 0; i < 4; i++) {
        int r0 = m0 + wm*64 + 16*i + (lane >> 2);
        #pragma unroll
        for (int hf = 0; hf < 2; hf++) {
            int row = r0 + hf*8;
            if (row >= rows) continue;
            float* crow;
            const float* rsd = nullptr;
            if (mode == 3) {
                int ent = list[e*TOK + row];
                crow = C + (size_t)(ent & 1)*TOK*N + (size_t)(ent >> 1)*N;
            } else if (mode == 0) {
                crow = C + (size_t)row * N;
                if (resid) rsd = resid + (size_t)row * N;
            } else if (mode == 5) {
                crow = C + (size_t)z*TOK*N + (size_t)row * N;
            } else {
                crow = C + ((size_t)e*TOK + row) * N;
            }
            #pragma unroll
            for (int j = 0; j < 4; j++) {
                int col = n0 + wn*32 + 8*j + 2*(lane & 3);
                float v0 = acc[i][j][hf*2 + 0];
                float v1 = acc[i][j][hf*2 + 1];
                v0 += be[col]; v1 += be[col + 1];
                if (rsd) { v0 += rsd[col]; v1 += rsd[col + 1]; }
                if (relu) { v0 = fmaxf(v0, 0.f); v1 = fmaxf(v1, 0.f); }
                *(float2*)(crow + col) = make_float2(v0, v1);
            }
        }
    }
}

// ================= hgemm_wl: BM=32 BN=256 BK=16, split-K, bf16 3-pass =========
// smem per CTA ~40 KB, 3 CTAs/SM target
#define AW_STRIDE 24        // bf16 elems (48 B)
#define BW_STRIDE 264
#define AHW 0
#define ALW 1536
#define BHW 3072
#define BLW 11520
#define BUFW 20224
#define SMEMW (2*BUFW + 256)

extern "C" __global__ void __launch_bounds__(256, 3)
hgemm_wl(const float* __restrict__ A, const float* __restrict__ W,
         float* __restrict__ part) {
    extern __shared__ char sm_raw[];
    char* sm = (char*)(((ull)sm_raw + 127) & ~127ULL);

    int n0 = blockIdx.x * 256;
    int z  = blockIdx.y;
    int tid = threadIdx.x;
    int lane = tid & 31, w = tid >> 5;

    const float* Ab = A + (size_t)z * WLKC;
    const float* Wb = W + (size_t)z * WLKC * NBIG;

    unsigned smbase = smem_u32(sm);
    int aq = lane >> 3, ar = lane & 7;
    unsigned a_base = smbase + AHW +
        (unsigned)(((ar + 8*(aq & 1)) * AW_STRIDE + 8*(aq >> 1)) * 2);
    unsigned b_base = smbase + BHW +
        (unsigned)(((lane & 15) * BW_STRIDE + w*32) * 2);

    float acc[2][4][4];
    #pragma unroll
    for (int i = 0; i < 2; i++)
        #pragma unroll
        for (int j = 0; j < 4; j++)
            #pragma unroll
            for (int q = 0; q < 4; q++) acc[i][j][q] = 0.f;

    const int nch = WLKC >> 4;   // 128 chunks of BK=16
    float4 av1; float4 bv[4];
    int am = tid >> 3, akq = tid & 3;         // A: 128 threads load (t<128)
    bool a_act = tid < 128;

    // prologue: chunk 0
    {
        if (a_act) av1 = *(const float4*)(Ab + (size_t)(tid >> 2)*NBIG + (tid & 3)*4);
        #pragma unroll
        for (int p = 0; p < 4; p++) {
            int s = tid + 256*p;
            bv[p] = *(const float4*)(Wb + (size_t)(s >> 6)*NBIG + n0 + (s & 63)*4);
        }
        char* bb = sm;
        unsigned h0, l0, h1, l1;
        if (a_act) {
            split_pair(av1.x, av1.y, h0, l0);
            split_pair(av1.z, av1.w, h1, l1);
            unsigned aoff = (unsigned)((tid >> 2)*(AW_STRIDE*2) + (tid & 3)*8);
            *(uint2*)(bb + AHW + aoff) = make_uint2(h0, h1);
            *(uint2*)(bb + ALW + aoff) = make_uint2(l0, l1);
        }
        #pragma unroll
        for (int p = 0; p < 4; p++) {
            int s = tid + 256*p;
            int n4 = s & 63, kk = s >> 6;
            split_pair(bv[p].x, bv[p].y, h0, l0);
            split_pair(bv[p].z, bv[p].w, h1, l1);
            unsigned boff = (unsigned)(kk*(BW_STRIDE*2) + n4*8);
            *(uint2*)(bb + BHW + boff) = make_uint2(h0, h1);
            *(uint2*)(bb + BLW + boff) = make_uint2(l0, l1);
        }
    }
    __syncthreads();

    for (int c = 0; c < nch; c++) {
        int buf = c & 1;
        bool has = (c + 1 < nch);
        if (has) {
            int kc = (c + 1) << 4;
            if (a_act) av1 = *(const float4*)(Ab + (size_t)(tid >> 2)*NBIG + kc + (tid & 3)*4);
            #pragma unroll
            for (int p = 0; p < 4; p++) {
                int s = tid + 256*p;
                bv[p] = *(const float4*)(Wb + (size_t)(kc + (s >> 6))*NBIG + n0 + (s & 63)*4);
            }
        }
        unsigned bufo = (unsigned)(buf * BUFW);
        {
            unsigned ah[2][4], al[2][4], bh[4][2], bl[4][2];
            unsigned ab = a_base + bufo;
            unsigned bb2 = b_base + bufo;
            #pragma unroll
            for (int i = 0; i < 2; i++) {
                ldm_x4(ah[i], ab + i*16*(AW_STRIDE*2));
                ldm_x4(al[i], ab + i*16*(AW_STRIDE*2) + (ALW - AHW));
            }
            #pragma unroll
            for (int j = 0; j < 4; j++) {
                ldm_x2t(bh[j], bb2 + j*16);
                ldm_x2t(bl[j], bb2 + j*16 + (BLW - BHW));
            }
            #pragma unroll
            for (int i = 0; i < 2; i++)
                #pragma unroll
                for (int j = 0; j < 4; j++) {
                    mma_bf16(acc[i][j], ah[i], bh[j]);
                    mma_bf16(acc[i][j], al[i], bh[j]);
                    mma_bf16(acc[i][j], ah[i], bl[j]);
                }
        }
        if (has) {
            char* bb = sm + (buf ^ 1) * BUFW;
            unsigned h0, l0, h1, l1;
            if (a_act) {
                split_pair(av1.x, av1.y, h0, l0);
                split_pair(av1.z, av1.w, h1, l1);
                unsigned aoff = (unsigned)((tid >> 2)*(AW_STRIDE*2) + (tid & 3)*8);
                *(uint2*)(bb + AHW + aoff) = make_uint2(h0, h1);
                *(uint2*)(bb + ALW + aoff) = make_uint2(l0, l1);
            }
            #pragma unroll
            for (int p = 0; p < 4; p++) {
                int s = tid + 256*p;
                int n4 = s & 63, kk = s >> 6;
                split_pair(bv[p].x, bv[p].y, h0, l0);
                split_pair(bv[p].z, bv[p].w, h1, l1);
                unsigned boff = (unsigned)(kk*(BW_STRIDE*2) + n4*8);
                *(uint2*)(bb + BHW + boff) = make_uint2(h0, h1);
                *(uint2*)(bb + BLW + boff) = make_uint2(l0, l1);
            }
        }
        __syncthreads();
    }

    float* pz = part + (size_t)z * 32 * NBIG;
    #pragma unroll
    for (int i = 0; i < 2; i++) {
        int r0 = 16*i + (lane >> 2);
        #pragma unroll
        for (int hf = 0; hf < 2; hf++) {
            int row = r0 + hf*8;
            float* crow = pz + (size_t)row * NBIG;
            #pragma unroll
            for (int j = 0; j < 4; j++) {
                int col = n0 + w*32 + 8*j + 2*(lane & 3);
                *(float2*)(crow + col) =
                    make_float2(acc[i][j][hf*2 + 0], acc[i][j][hf*2 + 1]);
            }
        }
    }
}

// ---------------- weight conversion ----------------
__global__ void cvt_moe_w(const float* __restrict__ W1, const float* __restrict__ Ws,
                          const float* __restrict__ W2, __half* __restrict__ o1,
                          __half* __restrict__ os, __half* __restrict__ o2) {
    size_t i = (size_t)blockIdx.x * 256 + threadIdx.x;
    const size_t n1 = (size_t)NEXP*DMODEL*FEXP;
    const size_t ns = (size_t)NEXP*FEXP*FEXP;
    if (i < n1)            o1[i]        = __float2half_rn(W1[i]);
    else if (i < n1 + ns)  os[i - n1]   = __float2half_rn(Ws[i - n1]);
    else                   o2[i-n1-ns]  = __float2half_rn(W2[i - n1 - ns]);
}
__global__ void cvt_qkvo_w(const float* __restrict__ Wq, const float* __restrict__ Wk,
                           const float* __restrict__ Wv, const float* __restrict__ Wo,
                           __half* __restrict__ oq, __half* __restrict__ ok,
                           __half* __restrict__ ov, __half* __restrict__ oo) {
    size_t i = (size_t)blockIdx.x * 256 + threadIdx.x;
    int seg = (int)(i >> 16);
    size_t j = i & 65535;
    const float* s = (seg == 0) ? Wq : (seg == 1) ? Wk : (seg == 2) ? Wv : Wo;
    __half* d = (seg == 0) ? oq : (seg == 1) ? ok : (seg == 2) ? ov : oo;
    d[j] = __float2half_rn(s[j]);
}

// ---------------- rmsnorm ----------------
__global__ void rmsnorm_kernel(const float* __restrict__ in, const float* __restrict__ w,
                               float* __restrict__ out) {
    int row = blockIdx.x, t = threadIdx.x;
    float v = in[(size_t)row*DMODEL + t];
    float ss = v*v;
    #pragma unroll
    for (int o = 16; o > 0; o >>= 1) ss += __shfl_xor_sync(0xffffffffu, ss, o);
    __shared__ float ws[8];
    if ((t & 31) == 0) ws[t >> 5] = ss;
    __syncthreads();
    float tot = 0.f;
    #pragma unroll
    for (int i = 0; i < 8; i++) tot += ws[i];
    float sc = rsqrtf(tot * (1.0f/256.0f) + 1e-5f);
    out[(size_t)row*DMODEL + t] = v * sc * w[t];
}

// ---------------- Wl split-K reduce ----------------
__global__ void wl_reduce(const float* __restrict__ part, const float* __restrict__ bl,
                          float* __restrict__ lat) {
    int i = blockIdx.x * 256 + threadIdx.x;
    float s = bl[i & (NBIG-1)];
    #pragma unroll
    for (int p = 0; p < WLSPLIT; p++) s += part[(size_t)p*32*NBIG + i];
    lat[i] = s;
}

// ---------------- attention ----------------
__global__ void attn_kernel(const float* __restrict__ q, const float* __restrict__ k,
                            const float* __restrict__ v, float* __restrict__ ao) {
    int bh = blockIdx.x;
    int b = bh >> 3, h = bh & 7;
    int s = threadIdx.x;
    __shared__ float ks[64][32];
    __shared__ float vs[64][32];
    for (int idx = s; idx < 2048; idx += 64) {
        int l = idx >> 5, d = idx & 31;
        size_t src = (size_t)(b*64 + l)*DMODEL + h*32 + d;
        ks[l][d] = k[src];
        vs[l][d] = v[src];
    }
    __syncthreads();

    float qr[32];
    const float* qp = q + (size_t)(b*64 + s)*DMODEL + h*32;
    #pragma unroll
    for (int d = 0; d < 32; d++) qr[d] = qp[d];

    // RoPE (bug-faithful)
    #pragma unroll
    for (int i = 0; i < 16; i++) {
        float fr = powf(10000.0f, -(float)i / 16.0f);
        float ang = (float)s * fr;
        float c = cosf(ang), sn = sinf(ang);
        float X = qr[2*i], Y = qr[2*i + 1];
        float nX = X*c - Y*sn;
        float nY = nX*sn + Y*c;
        qr[2*i] = nX; qr[2*i + 1] = nY;
    }

    const float scale = 0.1767766952966369f;
    float sc[64];
    float mx = -1e30f;
    #pragma unroll
    for (int l = 0; l < 64; l++) {
        float p = 0.f;
        #pragma unroll
        for (int d = 0; d < 32; d++) p += qr[d] * ks[l][d];
        p *= scale;
        sc[l] = p;
        mx = fmaxf(mx, p);
    }
    float se = 0.f;
    #pragma unroll
    for (int l = 0; l < 64; l++) { sc[l] = __expf(sc[l] - mx); se += sc[l]; }
    float inv = 1.0f / se;

    float* op = ao + (size_t)(b*64 + s)*DMODEL + h*32;
    #pragma unroll
    for (int d = 0; d < 32; d++) {
        float a = 0.f;
        #pragma unroll
        for (int l = 0; l < 64; l++) a += sc[l] * vs[l][d];
        op[d] = a * inv;
    }
}

// ---------------- router ----------------
__global__ void zero_cnt_kernel(int* cnt) { if (threadIdx.x < NEXP) cnt[threadIdx.x] = 0; }

__global__ void route_kernel(const float* __restrict__ y2, const float* __restrict__ rw,
                             const float* __restrict__ rb, float* __restrict__ topv,
                             int* __restrict__ cnt, int* __restrict__ list) {
    int tok = blockIdx.x, lane = threadIdx.x;
    float xv[8];
    #pragma unroll
    for (int j = 0; j < 8; j++) xv[j] = y2[(size_t)tok*DMODEL + j*32 + lane];
    float lg[8];
    #pragma unroll
    for (int e = 0; e < 8; e++) {
        float p = 0.f;
        #pragma unroll
        for (int j = 0; j < 8; j++) p += xv[j] * rw[(j*32 + lane)*NEXP + e];
        #pragma unroll
        for (int o = 16; o > 0; o >>= 1) p += __shfl_xor_sync(0xffffffffu, p, o);
        lg[e] = p;
    }
    if (lane == 0) {
        float mx = -1e30f;
        #pragma unroll
        for (int e = 0; e < 8; e++) { lg[e] += rb[e]; mx = fmaxf(mx, lg[e]); }
        float se = 0.f, pr[8];
        #pragma unroll
        for (int e = 0; e < 8; e++) { pr[e] = __expf(lg[e] - mx); se += pr[e]; }
        float inv = 1.0f / se;
        #pragma unroll
        for (int e = 0; e < 8; e++) pr[e] *= inv;
        int b0 = 0; float v0 = -1.f;
        #pragma unroll
        for (int e = 0; e < 8; e++) if (pr[e] > v0) { v0 = pr[e]; b0 = e; }
        int b1 = -1; float v1 = -1.f;
        #pragma unroll
        for (int e = 0; e < 8; e++) if (e != b0 && pr[e] > v1) { v1 = pr[e]; b1 = e; }
        topv[tok*2 + 0] = v0;
        topv[tok*2 + 1] = v1;
        int p0 = atomicAdd(&cnt[b0], 1); list[b0*TOK + p0] = tok*2;
        int p1 = atomicAdd(&cnt[b1], 1); list[b1*TOK + p1] = tok*2 + 1;
    }
}

// ---------------- combine ----------------
__global__ void combine_kernel(const float* __restrict__ x2, const float* __restrict__ topv,
                               const float* __restrict__ eo, float* __restrict__ out) {
    int tok = blockIdx.x, d = threadIdx.x;
    size_t i = (size_t)tok*DMODEL + d;
    out[i] = x2[i] + topv[tok*2] * eo[i] + topv[tok*2 + 1] * eo[(size_t)TOK*DMODEL + i];
}

// ---------------- host ----------------
extern "C" void kernel_launch(void* const* d_in, const int* in_sizes, int n_in,
                              void* d_out, int out_size) {
    const float* x   = (const float*)d_in[0];
    const float* r1w = (const float*)d_in[1];
    const float* Wl  = (const float*)d_in[2];
    const float* bl  = (const float*)d_in[3];
    const float* Wq  = (const float*)d_in[4];
    const float* bq  = (const float*)d_in[5];
    const float* Wk  = (const float*)d_in[6];
    const float* bk  = (const float*)d_in[7];
    const float* Wv  = (const float*)d_in[8];
    const float* bv  = (const float*)d_in[9];
    const float* Wo  = (const float*)d_in[10];
    const float* bo  = (const float*)d_in[11];
    const float* r2w = (const float*)d_in[12];
    const float* rw  = (const float*)d_in[13];
    const float* rb  = (const float*)d_in[14];
    const float* W1  = (const float*)d_in[15];
    const float* b1  = (const float*)d_in[16];
    const float* Wsx = (const float*)d_in[17];
    const float* bs  = (const float*)d_in[18];
    const float* W2  = (const float*)d_in[19];
    const float* b2  = (const float*)d_in[20];

    float *y1, *part, *lat, *qkv, *ao, *x2, *y2, *topv, *h1, *h2, *eo;
    __half *w116, *ws16, *w216, *wq16, *wk16, *wv16, *wo16;
    int *cnt, *list;
    cudaGetSymbolAddress((void**)&y1,   g_y1);
    cudaGetSymbolAddress((void**)&part, g_part);
    cudaGetSymbolAddress((void**)&lat,  g_lat);
    cudaGetSymbolAddress((void**)&qkv,  g_qkv);
    cudaGetSymbolAddress((void**)&ao,   g_ao);
    cudaGetSymbolAddress((void**)&x2,   g_x2);
    cudaGetSymbolAddress((void**)&y2,   g_y2);
    cudaGetSymbolAddress((void**)&topv, g_topv);
    cudaGetSymbolAddress((void**)&cnt,  g_cnt);
    cudaGetSymbolAddress((void**)&list, g_list);
    cudaGetSymbolAddress((void**)&h1,   g_h1);
    cudaGetSymbolAddress((void**)&h2,   g_h2);
    cudaGetSymbolAddress((void**)&eo,   g_eo);
    cudaGetSymbolAddress((void**)&w116, g_w116);
    cudaGetSymbolAddress((void**)&ws16, g_ws16);
    cudaGetSymbolAddress((void**)&w216, g_w216);
    cudaGetSymbolAddress((void**)&wq16, g_wq16);
    cudaGetSymbolAddress((void**)&wk16, g_wk16);
    cudaGetSymbolAddress((void**)&wv16, g_wv16);
    cudaGetSymbolAddress((void**)&wo16, g_wo16);

    static int smem_set = 0;
    if (!smem_set) {
        cudaFuncSetAttribute(hgemm,    cudaFuncAttributeMaxDynamicSharedMemorySize, SMEM128);
        cudaFuncSetAttribute(hgemm_wl, cudaFuncAttributeMaxDynamicSharedMemorySize, SMEMW);
        smem_set = 1;
    }

    // weight conversions
    cvt_qkvo_w<<<1024, 256>>>(Wq, Wk, Wv, Wo, wq16, wk16, wv16, wo16);
    cvt_moe_w<<<49152, 256>>>(W1, Wsx, W2, w116, ws16, w216);

    // --- MHLA ---
    rmsnorm_kernel<<<TOK, 256>>>(x, r1w, y1);
    hgemm_wl<<<dim3(64, WLSPLIT), 256, SMEMW>>>(y1, Wl, part);
    wl_reduce<<<TOK, 256>>>(part, bl, lat);
    hgemm<<<dim3(2, 16, 3), 256, SMEM128>>>(y1, wq16, bq, nullptr, qkv,
        TOK, DMODEL, DMODEL, DMODEL, nullptr, nullptr, 5, 0,
        lat, wk16, wv16, bk, bv);
    attn_kernel<<<256, 64>>>(qkv, qkv + (size_t)TOK*DMODEL, qkv + 2*(size_t)TOK*DMODEL, ao);
    hgemm<<<dim3(2, 16, 1), 256, SMEM128>>>(ao, wo16, bo, x, x2,
        TOK, DMODEL, DMODEL, DMODEL, nullptr, nullptr, 0, 0,
        nullptr, nullptr, nullptr, nullptr, nullptr);

    // --- MoE ---
    rmsnorm_kernel<<<TOK, 256>>>(x2, r2w, y2);
    zero_cnt_kernel<<<1, 32>>>(cnt);
    route_kernel<<<TOK, 32>>>(y2, rw, rb, topv, cnt, list);
    hgemm<<<dim3(8, 16, NEXP), 256, SMEM128>>>(y2, w116, b1, nullptr, h1,
        0, FEXP, DMODEL, DMODEL, list, cnt, 1, 0,
        nullptr, nullptr, nullptr, nullptr, nullptr);
    hgemm<<<dim3(8, 16, NEXP), 256, SMEM128>>>(h1, ws16, bs, nullptr, h2,
        0, FEXP, FEXP, FEXP, list, cnt, 2, 1,
        nullptr, nullptr, nullptr, nullptr, nullptr);
    hgemm<<<dim3(2, 16, NEXP), 256, SMEM128>>>(h2, w216, b2, nullptr, eo,
        0, DMODEL, FEXP, FEXP, list, cnt, 3, 0,
        nullptr, nullptr, nullptr, nullptr, nullptr);
    combine_kernel<<<TOK, 256>>>(x2, topv, eo, (float*)d_out);
}

// round 10
// speedup vs baseline: 1.1712x; 1.1712x over previous
#include <cuda_runtime.h>
#include <cuda_bf16.h>
#include <cuda_fp16.h>

typedef unsigned long long ull;

// B=32, S=64, D=256, H=8, E=8, topk=2, F=1024, LATENT=64, HD=32
#define TOK      2048
#define DMODEL   256
#define NBIG     16384
#define FEXP     1024
#define NEXP     8
#define WLSPLIT  4
#define WLKC     (NBIG/WLSPLIT)   // 4096
#define HPLANE   ((size_t)NEXP*TOK*FEXP)

// ---------------- scratch ----------------
__device__ float  g_y1 [TOK*DMODEL];
__device__ float  g_part[WLSPLIT*32*NBIG];
__device__ float  g_lat[TOK*DMODEL];
__device__ float  g_qkv[3*TOK*DMODEL];
__device__ float  g_ao [TOK*DMODEL];
__device__ float  g_x2 [TOK*DMODEL];
__device__ float  g_y2 [TOK*DMODEL];
__device__ float  g_topv[TOK*2];
__device__ int    g_cnt[NEXP];
__device__ int    g_list[NEXP*TOK];
__device__ float  g_eo [2*TOK*DMODEL];
__device__ __align__(16) __half g_h1x[2*NEXP*TOK*FEXP];   // hi plane, lo plane
__device__ __align__(16) __half g_h2x[2*NEXP*TOK*FEXP];
__device__ __align__(16) __half g_w116[NEXP*DMODEL*FEXP];
__device__ __align__(16) __half g_ws16[NEXP*FEXP*FEXP];
__device__ __align__(16) __half g_w216[NEXP*FEXP*DMODEL];
__device__ __align__(16) __half g_wq16[DMODEL*DMODEL];
__device__ __align__(16) __half g_wk16[DMODEL*DMODEL];
__device__ __align__(16) __half g_wv16[DMODEL*DMODEL];
__device__ __align__(16) __half g_wo16[DMODEL*DMODEL];

// ---------------- helpers ----------------
__device__ __forceinline__ unsigned smem_u32(const void* p) {
    return (unsigned)__cvta_generic_to_shared(p);
}
#define CPA16(dst, src) asm volatile("cp.async.cg.shared.global [%0], [%1], 16;" :: "r"(dst), "l"(src))
#define CPA_COMMIT()    asm volatile("cp.async.commit_group;")
#define CPA_WAIT0()     asm volatile("cp.async.wait_group 0;")
__device__ __forceinline__ void ldm_x4(unsigned* r, unsigned addr) {
    asm volatile("ldmatrix.sync.aligned.m8n8.x4.shared.b16 {%0,%1,%2,%3}, [%4];"
        : "=r"(r[0]), "=r"(r[1]), "=r"(r[2]), "=r"(r[3]) : "r"(addr));
}
__device__ __forceinline__ void ldm_x4t(unsigned* r, unsigned addr) {
    asm volatile("ldmatrix.sync.aligned.m8n8.x4.trans.shared.b16 {%0,%1,%2,%3}, [%4];"
        : "=r"(r[0]), "=r"(r[1]), "=r"(r[2]), "=r"(r[3]) : "r"(addr));
}
__device__ __forceinline__ void ldm_x2t(unsigned* r, unsigned addr) {
    asm volatile("ldmatrix.sync.aligned.m8n8.x2.trans.shared.b16 {%0,%1}, [%2];"
        : "=r"(r[0]), "=r"(r[1]) : "r"(addr));
}
__device__ __forceinline__ void mma_bf16(float* c, const unsigned* a, const unsigned* b) {
    asm volatile("mma.sync.aligned.m16n8k16.row.col.f32.bf16.bf16.f32 "
        "{%0,%1,%2,%3}, {%4,%5,%6,%7}, {%8,%9}, {%0,%1,%2,%3};"
        : "+f"(c[0]), "+f"(c[1]), "+f"(c[2]), "+f"(c[3])
        : "r"(a[0]), "r"(a[1]), "r"(a[2]), "r"(a[3]), "r"(b[0]), "r"(b[1]));
}
__device__ __forceinline__ void mma_f16(float* c, const unsigned* a, const unsigned* b) {
    asm volatile("mma.sync.aligned.m16n8k16.row.col.f32.f16.f16.f32 "
        "{%0,%1,%2,%3}, {%4,%5,%6,%7}, {%8,%9}, {%0,%1,%2,%3};"
        : "+f"(c[0]), "+f"(c[1]), "+f"(c[2]), "+f"(c[3])
        : "r"(a[0]), "r"(a[1]), "r"(a[2]), "r"(a[3]), "r"(b[0]), "r"(b[1]));
}
// bf16 split (Wl kernel)
__device__ __forceinline__ void split_pair(float x, float y, unsigned& hi, unsigned& lo) {
    unsigned ux = __float_as_uint(x), uy = __float_as_uint(y);
    hi = __byte_perm(ux, uy, 0x7632);
    float lx = x - __uint_as_float(ux & 0xFFFF0000u);
    float ly = y - __uint_as_float(uy & 0xFFFF0000u);
    asm("cvt.rn.bf16x2.f32 %0, %1, %2;" : "=r"(lo) : "f"(ly), "f"(lx));
}
// fp16 pack / splits
__device__ __forceinline__ unsigned pack_f16(float x, float y) {
    unsigned r;
    asm("cvt.rn.f16x2.f32 %0, %1, %2;" : "=r"(r) : "f"(y), "f"(x));
    return r;
}
__device__ __forceinline__ void split_pair_f16(float x, float y, unsigned& hi, unsigned& lo) {
    hi = pack_f16(x, y);
    __half2 h = *reinterpret_cast<__half2*>(&hi);
    float2 hf = __half22float2(h);
    lo = pack_f16(x - hf.x, y - hf.y);
}

// ================= hgemm: BM=128 BN=128 BK=32, fp32 A (split) + fp16 W ==========
// mode 0: C[r]=A[r]@W+bias(+resid) fp32   mode 1: gather via list>>1 -> fp16 planes outh
// mode 5: fused QKV (z selects A/W/bias), fp32 C slice z*TOK*N
#define A128_STRIDE 40      // f16 elems (80 B)
#define B128_STRIDE 136     // f16 elems (272 B)
#define AH128 0
#define AL128 10240
#define BH128 20480
#define BUF128 29184        // AH + AL + BH(8704)
#define ROWP128 (2*BUF128)
#define SMEM128 (2*BUF128 + 1024 + 256)

extern "C" __global__ void __launch_bounds__(256)
hgemm(const float* __restrict__ A, const __half* __restrict__ W16,
      const float* __restrict__ bias, const float* __restrict__ resid,
      float* __restrict__ C, __half* __restrict__ outh, size_t oloff,
      int M, int N, int K, int lda,
      const int* __restrict__ list, const int* __restrict__ cntp,
      int mode, int relu,
      const float* A2, const __half* Wk16, const __half* Wv16,
      const float* bk2, const float* bv3) {
    extern __shared__ char sm_raw[];
    char* sm = (char*)(((ull)sm_raw + 127) & ~127ULL);

    int z = blockIdx.z;
    int e = (mode == 1) ? z : 0;
    const float* Asrc = A;
    const __half* Wsrc = W16;
    const float* bsrc = bias;
    if (mode == 5 && z > 0) {
        Asrc = A2;
        Wsrc = (z == 1) ? Wk16 : Wv16;
        bsrc = (z == 1) ? bk2 : bv3;
    }
    int rows = cntp ? cntp[e] : M;
    int m0 = blockIdx.y * 128;
    if (m0 >= rows) return;
    int n0 = blockIdx.x * 128;
    int tid = threadIdx.x;
    int lane = tid & 31, w = tid >> 5;
    int wm = w & 1, wn = w >> 1;

    const __half* We = Wsrc + (size_t)e * K * N;
    const float* be = bsrc + (size_t)e * N;

    const float** rowp = (const float**)(sm + ROWP128);
    if (tid < 128) {
        int r = m0 + tid;
        const float* p = nullptr;
        if (r < rows) {
            if (mode == 1) p = Asrc + (size_t)(list[e*TOK + r] >> 1) * lda;
            else           p = Asrc + (size_t)r * lda;
        }
        rowp[tid] = p;
    }
    __syncthreads();

    unsigned smbase = smem_u32(sm);
    int aq = lane >> 3, ar = lane & 7;
    unsigned a_base = smbase + AH128 +
        (unsigned)(((wm*64 + ar + 8*(aq & 1)) * A128_STRIDE + 8*(aq >> 1)) * 2);
    int bt = lane >> 3;
    int bkrow = (bt & 1)*8 + (lane & 7);
    int bnoff = (bt >> 1)*8;
    unsigned b_base = smbase + BH128 +
        (unsigned)((bkrow * B128_STRIDE + wn*32 + bnoff) * 2);

    float acc[4][4][4];
    #pragma unroll
    for (int i = 0; i < 4; i++)
        #pragma unroll
        for (int j = 0; j < 4; j++)
            #pragma unroll
            for (int q = 0; q < 4; q++) acc[i][j][q] = 0.f;

    int nch = K >> 5;
    float4 av[4];

    // ---- prologue: chunk 0 ----
    {
        unsigned bb = smbase;
        #pragma unroll
        for (int p = 0; p < 2; p++) {
            int s = tid + 256*p;
            CPA16(bb + BH128 + (s >> 4)*272 + (s & 15)*16,
                  (const char*)(We + (size_t)(s >> 4)*N + n0 + (s & 15)*8));
        }
        CPA_COMMIT();
        #pragma unroll
        for (int p = 0; p < 4; p++) {
            int s = tid + 256*p;
            const float* rp = rowp[s >> 3];
            av[p] = rp ? *(const float4*)(rp + (s & 7)*4) : make_float4(0.f,0.f,0.f,0.f);
        }
        char* bc = sm;
        #pragma unroll
        for (int p = 0; p < 4; p++) {
            int s = tid + 256*p;
            int m = s >> 3, kq = s & 7;
            unsigned h0, l0, h1, l1;
            split_pair_f16(av[p].x, av[p].y, h0, l0);
            split_pair_f16(av[p].z, av[p].w, h1, l1);
            unsigned aoff = (unsigned)(m*(A128_STRIDE*2) + kq*8);
            *(uint2*)(bc + AH128 + aoff) = make_uint2(h0, h1);
            *(uint2*)(bc + AL128 + aoff) = make_uint2(l0, l1);
        }
        CPA_WAIT0();
        __syncthreads();
    }

    for (int c = 0; c < nch; c++) {
        int buf = c & 1;
        bool has = (c + 1 < nch);
        if (has) {
            int kc = (c + 1) << 5;
            unsigned bb = smbase + (unsigned)((buf ^ 1) * BUF128);
            #pragma unroll
            for (int p = 0; p < 2; p++) {
                int s = tid + 256*p;
                CPA16(bb + BH128 + (s >> 4)*272 + (s & 15)*16,
                      (const char*)(We + (size_t)(kc + (s >> 4))*N + n0 + (s & 15)*8));
            }
            CPA_COMMIT();
            #pragma unroll
            for (int p = 0; p < 4; p++) {
                int s = tid + 256*p;
                const float* rp = rowp[s >> 3];
                av[p] = rp ? *(const float4*)(rp + kc + (s & 7)*4) : make_float4(0.f,0.f,0.f,0.f);
            }
        }
        // ---- compute on buf ----
        unsigned bufo = (unsigned)(buf * BUF128);
        #pragma unroll
        for (int ks = 0; ks < 2; ks++) {
            unsigned ah[4][4], al[4][4], bf[2][4];
            unsigned ab = a_base + bufo + ks*32;
            unsigned bb2 = b_base + bufo + ks*16*(B128_STRIDE*2);
            #pragma unroll
            for (int i = 0; i < 4; i++) {
                ldm_x4(ah[i], ab + i*16*(A128_STRIDE*2));
                ldm_x4(al[i], ab + i*16*(A128_STRIDE*2) + (AL128 - AH128));
            }
            #pragma unroll
            for (int jj = 0; jj < 2; jj++) ldm_x4t(bf[jj], bb2 + jj*32);
            #pragma unroll
            for (int i = 0; i < 4; i++)
                #pragma unroll
                for (int j = 0; j < 4; j++) {
                    mma_f16(acc[i][j], ah[i], &bf[j >> 1][(j & 1)*2]);
                    mma_f16(acc[i][j], al[i], &bf[j >> 1][(j & 1)*2]);
                }
        }
        if (has) {
            char* bc = sm + (buf ^ 1) * BUF128;
            #pragma unroll
            for (int p = 0; p < 4; p++) {
                int s = tid + 256*p;
                int m = s >> 3, kq = s & 7;
                unsigned h0, l0, h1, l1;
                split_pair_f16(av[p].x, av[p].y, h0, l0);
                split_pair_f16(av[p].z, av[p].w, h1, l1);
                unsigned aoff = (unsigned)(m*(A128_STRIDE*2) + kq*8);
                *(uint2*)(bc + AH128 + aoff) = make_uint2(h0, h1);
                *(uint2*)(bc + AL128 + aoff) = make_uint2(l0, l1);
            }
            CPA_WAIT0();
        }
        __syncthreads();
    }

    // ---- epilogue ----
    #pragma unroll
    for (int i = 0; i < 4; i++) {
        int r0 = m0 + wm*64 + 16*i + (lane >> 2);
        #pragma unroll
        for (int hf = 0; hf < 2; hf++) {
            int row = r0 + hf*8;
            if (row >= rows) continue;
            float* crow = nullptr;
            __half* orow = nullptr;
            const float* rsd = nullptr;
            if (mode == 0) {
                crow = C + (size_t)row * N;
                if (resid) rsd = resid + (size_t)row * N;
            } else if (mode == 5) {
                crow = C + (size_t)z*TOK*N + (size_t)row * N;
            } else { // mode 1: fp16 planes
                orow = outh + ((size_t)e*TOK + row) * N;
            }
            #pragma unroll
            for (int j = 0; j < 4; j++) {
                int col = n0 + wn*32 + 8*j + 2*(lane & 3);
                float v0 = acc[i][j][hf*2 + 0];
                float v1 = acc[i][j][hf*2 + 1];
                v0 += be[col]; v1 += be[col + 1];
                if (rsd) { v0 += rsd[col]; v1 += rsd[col + 1]; }
                if (relu) { v0 = fmaxf(v0, 0.f); v1 = fmaxf(v1, 0.f); }
                if (crow) {
                    *(float2*)(crow + col) = make_float2(v0, v1);
                } else {
                    unsigned hp, lp;
                    split_pair_f16(v0, v1, hp, lp);
                    *(unsigned*)(orow + col) = hp;
                    *(unsigned*)(orow + oloff + col) = lp;
                }
            }
        }
    }
}

// ================= hgemm_f16a: A already fp16 h/l planes; pure-copy staging ======
// mode 2: A at e*TOK -> fp16 planes out (+relu)   mode 3: A at e*TOK -> fp32 scatter
extern "C" __global__ void __launch_bounds__(256)
hgemm_f16a(const __half* __restrict__ Ah, size_t aplane,
           const __half* __restrict__ W16, const float* __restrict__ bias,
           float* __restrict__ C, __half* __restrict__ outh, size_t oplane,
           int N, int K, int lda,
           const int* __restrict__ list, const int* __restrict__ cntp,
           int mode, int relu) {
    extern __shared__ char sm_raw[];
    char* sm = (char*)(((ull)sm_raw + 127) & ~127ULL);

    int e = blockIdx.z;
    int rows = cntp[e];
    int m0 = blockIdx.y * 128;
    if (m0 >= rows) return;
    int n0 = blockIdx.x * 128;
    int tid = threadIdx.x;
    int lane = tid & 31, w = tid >> 5;
    int wm = w & 1, wn = w >> 1;

    const __half* We = W16 + (size_t)e * K * N;
    const float* be = bias + (size_t)e * N;
    const __half* Abase = Ah + ((size_t)e*TOK + m0) * lda;

    unsigned smbase = smem_u32(sm);
    int aq = lane >> 3, ar = lane & 7;
    unsigned a_base = smbase + AH128 +
        (unsigned)(((wm*64 + ar + 8*(aq & 1)) * A128_STRIDE + 8*(aq >> 1)) * 2);
    int bt = lane >> 3;
    int bkrow = (bt & 1)*8 + (lane & 7);
    int bnoff = (bt >> 1)*8;
    unsigned b_base = smbase + BH128 +
        (unsigned)((bkrow * B128_STRIDE + wn*32 + bnoff) * 2);

    float acc[4][4][4];
    #pragma unroll
    for (int i = 0; i < 4; i++)
        #pragma unroll
        for (int j = 0; j < 4; j++)
            #pragma unroll
            for (int q = 0; q < 4; q++) acc[i][j][q] = 0.f;

    int arow = tid >> 2, aqw = tid & 3;     // 512 granules per plane, 2/thread
    int nch = K >> 5;

    // stage chunk into buffer bb (cp.async only)
    // A plane h: granules (tid, tid+256); plane l same; B: (tid, tid+256)
    {
        unsigned bb = smbase;
        #pragma unroll
        for (int p = 0; p < 2; p++) {
            int g = tid + 256*p;
            int m = g >> 2, q = g & 3;
            unsigned aoff = (unsigned)(m*(A128_STRIDE*2) + q*16);
            CPA16(bb + AH128 + aoff, (const char*)(Abase + (size_t)m*lda + q*8));
            CPA16(bb + AL128 + aoff, (const char*)(Abase + aplane + (size_t)m*lda + q*8));
            int s = g;
            CPA16(bb + BH128 + (s >> 4)*272 + (s & 15)*16,
                  (const char*)(We + (size_t)(s >> 4)*N + n0 + (s & 15)*8));
        }
        CPA_COMMIT();
        CPA_WAIT0();
        __syncthreads();
    }

    for (int c = 0; c < nch; c++) {
        int buf = c & 1;
        bool has = (c + 1 < nch);
        if (has) {
            int kc = (c + 1) << 5;
            unsigned bb = smbase + (unsigned)((buf ^ 1) * BUF128);
            #pragma unroll
            for (int p = 0; p < 2; p++) {
                int g = tid + 256*p;
                int m = g >> 2, q = g & 3;
                unsigned aoff = (unsigned)(m*(A128_STRIDE*2) + q*16);
                CPA16(bb + AH128 + aoff, (const char*)(Abase + (size_t)m*lda + kc + q*8));
                CPA16(bb + AL128 + aoff, (const char*)(Abase + aplane + (size_t)m*lda + kc + q*8));
                int s = g;
                CPA16(bb + BH128 + (s >> 4)*272 + (s & 15)*16,
                      (const char*)(We + (size_t)(kc + (s >> 4))*N + n0 + (s & 15)*8));
            }
            CPA_COMMIT();
        }
        unsigned bufo = (unsigned)(buf * BUF128);
        #pragma unroll
        for (int ks = 0; ks < 2; ks++) {
            unsigned ah[4][4], al[4][4], bf[2][4];
            unsigned ab = a_base + bufo + ks*32;
            unsigned bb2 = b_base + bufo + ks*16*(B128_STRIDE*2);
            #pragma unroll
            for (int i = 0; i < 4; i++) {
                ldm_x4(ah[i], ab + i*16*(A128_STRIDE*2));
                ldm_x4(al[i], ab + i*16*(A128_STRIDE*2) + (AL128 - AH128));
            }
            #pragma unroll
            for (int jj = 0; jj < 2; jj++) ldm_x4t(bf[jj], bb2 + jj*32);
            #pragma unroll
            for (int i = 0; i < 4; i++)
                #pragma unroll
                for (int j = 0; j < 4; j++) {
                    mma_f16(acc[i][j], ah[i], &bf[j >> 1][(j & 1)*2]);
                    mma_f16(acc[i][j], al[i], &bf[j >> 1][(j & 1)*2]);
                }
        }
        if (has) CPA_WAIT0();
        __syncthreads();
    }

    // ---- epilogue ----
    #pragma unroll
    for (int i = 0; i < 4; i++) {
        int r0 = m0 + wm*64 + 16*i + (lane >> 2);
        #pragma unroll
        for (int hf = 0; hf < 2; hf++) {
            int row = r0 + hf*8;
            if (row >= rows) continue;
            float* crow = nullptr;
            __half* orow = nullptr;
            if (mode == 3) {
                int ent = list[e*TOK + row];
                crow = C + (size_t)(ent & 1)*TOK*N + (size_t)(ent >> 1)*N;
            } else {
                orow = outh + ((size_t)e*TOK + row) * N;
            }
            #pragma unroll
            for (int j = 0; j < 4; j++) {
                int col = n0 + wn*32 + 8*j + 2*(lane & 3);
                float v0 = acc[i][j][hf*2 + 0];
                float v1 = acc[i][j][hf*2 + 1];
                v0 += be[col]; v1 += be[col + 1];
                if (relu) { v0 = fmaxf(v0, 0.f); v1 = fmaxf(v1, 0.f); }
                if (crow) {
                    *(float2*)(crow + col) = make_float2(v0, v1);
                } else {
                    unsigned hp, lp;
                    split_pair_f16(v0, v1, hp, lp);
                    *(unsigned*)(orow + col) = hp;
                    *(unsigned*)(orow + oplane + col) = lp;
                }
            }
        }
    }
}

// ================= hgemm_wl: BM=32 BN=256 BK=32, split-K=4, bf16 3-pass =========
#define AW_STRIDE 40
#define BW_STRIDE 264
#define AHW 0
#define ALW 2560
#define BHW 5120
#define BLW 22016
#define BUFW 38912
#define SMEMW (2*BUFW + 256)

extern "C" __global__ void __launch_bounds__(256)
hgemm_wl(const float* __restrict__ A, const float* __restrict__ W,
         float* __restrict__ part) {
    extern __shared__ char sm_raw[];
    char* sm = (char*)(((ull)sm_raw + 127) & ~127ULL);

    int n0 = blockIdx.x * 256;
    int z  = blockIdx.y;
    int tid = threadIdx.x;
    int lane = tid & 31, w = tid >> 5;

    const float* Ab = A + (size_t)z * WLKC;
    const float* Wb = W + (size_t)z * WLKC * NBIG;

    unsigned smbase = smem_u32(sm);
    int aq = lane >> 3, ar = lane & 7;
    unsigned a_base = smbase + AHW +
        (unsigned)(((ar + 8*(aq & 1)) * AW_STRIDE + 8*(aq >> 1)) * 2);
    unsigned b_base = smbase + BHW +
        (unsigned)(((lane & 15) * BW_STRIDE + w*32) * 2);

    float acc[2][4][4];
    #pragma unroll
    for (int i = 0; i < 2; i++)
        #pragma unroll
        for (int j = 0; j < 4; j++)
            #pragma unroll
            for (int q = 0; q < 4; q++) acc[i][j][q] = 0.f;

    const int nch = WLKC >> 5;   // 128
    float4 av1; float4 bv[8];

    {
        int m = tid >> 3, kq = tid & 7;
        av1 = *(const float4*)(Ab + (size_t)m*NBIG + kq*4);
        #pragma unroll
        for (int p = 0; p < 8; p++) {
            int s = tid + 256*p;
            bv[p] = *(const float4*)(Wb + (size_t)(s >> 6)*NBIG + n0 + (s & 63)*4);
        }
        char* bb = sm;
        unsigned h0, l0, h1, l1;
        split_pair(av1.x, av1.y, h0, l0);
        split_pair(av1.z, av1.w, h1, l1);
        unsigned aoff = (unsigned)(m*(AW_STRIDE*2) + kq*8);
        *(uint2*)(bb + AHW + aoff) = make_uint2(h0, h1);
        *(uint2*)(bb + ALW + aoff) = make_uint2(l0, l1);
        #pragma unroll
        for (int p = 0; p < 8; p++) {
            int s = tid + 256*p;
            int n4 = s & 63, kk = s >> 6;
            split_pair(bv[p].x, bv[p].y, h0, l0);
            split_pair(bv[p].z, bv[p].w, h1, l1);
            unsigned boff = (unsigned)(kk*(BW_STRIDE*2) + n4*8);
            *(uint2*)(bb + BHW + boff) = make_uint2(h0, h1);
            *(uint2*)(bb + BLW + boff) = make_uint2(l0, l1);
        }
    }
    __syncthreads();

    for (int c = 0; c < nch; c++) {
        int buf = c & 1;
        bool has = (c + 1 < nch);
        if (has) {
            int kc = (c + 1) << 5;
            int m = tid >> 3, kq = tid & 7;
            av1 = *(const float4*)(Ab + (size_t)m*NBIG + kc + kq*4);
            #pragma unroll
            for (int p = 0; p < 8; p++) {
                int s = tid + 256*p;
                bv[p] = *(const float4*)(Wb + (size_t)(kc + (s >> 6))*NBIG + n0 + (s & 63)*4);
            }
        }
        unsigned bufo = (unsigned)(buf * BUFW);
        #pragma unroll
        for (int ks = 0; ks < 2; ks++) {
            unsigned ah[2][4], al[2][4], bh[4][2], bl[4][2];
            unsigned ab = a_base + bufo + ks*32;
            unsigned bb2 = b_base + bufo + ks*16*(BW_STRIDE*2);
            #pragma unroll
            for (int i = 0; i < 2; i++) {
                ldm_x4(ah[i], ab + i*16*(AW_STRIDE*2));
                ldm_x4(al[i], ab + i*16*(AW_STRIDE*2) + (ALW - AHW));
            }
            #pragma unroll
            for (int j = 0; j < 4; j++) {
                ldm_x2t(bh[j], bb2 + j*16);
                ldm_x2t(bl[j], bb2 + j*16 + (BLW - BHW));
            }
            #pragma unroll
            for (int i = 0; i < 2; i++)
                #pragma unroll
                for (int j = 0; j < 4; j++) {
                    mma_bf16(acc[i][j], ah[i], bh[j]);
                    mma_bf16(acc[i][j], al[i], bh[j]);
                    mma_bf16(acc[i][j], ah[i], bl[j]);
                }
        }
        if (has) {
            char* bb = sm + (buf ^ 1) * BUFW;
            int m = tid >> 3, kq = tid & 7;
            unsigned h0, l0, h1, l1;
            split_pair(av1.x, av1.y, h0, l0);
            split_pair(av1.z, av1.w, h1, l1);
            unsigned aoff = (unsigned)(m*(AW_STRIDE*2) + kq*8);
            *(uint2*)(bb + AHW + aoff) = make_uint2(h0, h1);
            *(uint2*)(bb + ALW + aoff) = make_uint2(l0, l1);
            #pragma unroll
            for (int p = 0; p < 8; p++) {
                int s = tid + 256*p;
                int n4 = s & 63, kk = s >> 6;
                split_pair(bv[p].x, bv[p].y, h0, l0);
                split_pair(bv[p].z, bv[p].w, h1, l1);
                unsigned boff = (unsigned)(kk*(BW_STRIDE*2) + n4*8);
                *(uint2*)(bb + BHW + boff) = make_uint2(h0, h1);
                *(uint2*)(bb + BLW + boff) = make_uint2(l0, l1);
            }
        }
        __syncthreads();
    }

    float* pz = part + (size_t)z * 32 * NBIG;
    #pragma unroll
    for (int i = 0; i < 2; i++) {
        int r0 = 16*i + (lane >> 2);
        #pragma unroll
        for (int hf = 0; hf < 2; hf++) {
            int row = r0 + hf*8;
            float* crow = pz + (size_t)row * NBIG;
            #pragma unroll
            for (int j = 0; j < 4; j++) {
                int col = n0 + w*32 + 8*j + 2*(lane & 3);
                *(float2*)(crow + col) =
                    make_float2(acc[i][j][hf*2 + 0], acc[i][j][hf*2 + 1]);
            }
        }
    }
}

// ---------------- weight conversion ----------------
__global__ void cvt_moe_w(const float* __restrict__ W1, const float* __restrict__ Ws,
                          const float* __restrict__ W2, __half* __restrict__ o1,
                          __half* __restrict__ os, __half* __restrict__ o2) {
    size_t i = (size_t)blockIdx.x * 256 + threadIdx.x;
    const size_t n1 = (size_t)NEXP*DMODEL*FEXP;
    const size_t ns = (size_t)NEXP*FEXP*FEXP;
    if (i < n1)            o1[i]        = __float2half_rn(W1[i]);
    else if (i < n1 + ns)  os[i - n1]   = __float2half_rn(Ws[i - n1]);
    else                   o2[i-n1-ns]  = __float2half_rn(W2[i - n1 - ns]);
}
__global__ void cvt_qkvo_w(const float* __restrict__ Wq, const float* __restrict__ Wk,
                           const float* __restrict__ Wv, const float* __restrict__ Wo,
                           __half* __restrict__ oq, __half* __restrict__ ok,
                           __half* __restrict__ ov, __half* __restrict__ oo) {
    size_t i = (size_t)blockIdx.x * 256 + threadIdx.x;
    int seg = (int)(i >> 16);
    size_t j = i & 65535;
    const float* s = (seg == 0) ? Wq : (seg == 1) ? Wk : (seg == 2) ? Wv : Wo;
    __half* d = (seg == 0) ? oq : (seg == 1) ? ok : (seg == 2) ? ov : oo;
    d[j] = __float2half_rn(s[j]);
}

// ---------------- rmsnorm ----------------
__global__ void rmsnorm_kernel(const float* __restrict__ in, const float* __restrict__ w,
                               float* __restrict__ out) {
    int row = blockIdx.x, t = threadIdx.x;
    float v = in[(size_t)row*DMODEL + t];
    float ss = v*v;
    #pragma unroll
    for (int o = 16; o > 0; o >>= 1) ss += __shfl_xor_sync(0xffffffffu, ss, o);
    __shared__ float ws[8];
    if ((t & 31) == 0) ws[t >> 5] = ss;
    __syncthreads();
    float tot = 0.f;
    #pragma unroll
    for (int i = 0; i < 8; i++) tot += ws[i];
    float sc = rsqrtf(tot * (1.0f/256.0f) + 1e-5f);
    out[(size_t)row*DMODEL + t] = v * sc * w[t];
}

// ---------------- Wl split-K reduce ----------------
__global__ void wl_reduce(const float* __restrict__ part, const float* __restrict__ bl,
                          float* __restrict__ lat) {
    int i = blockIdx.x * 256 + threadIdx.x;
    float s = bl[i & (NBIG-1)];
    #pragma unroll
    for (int p = 0; p < WLSPLIT; p++) s += part[(size_t)p*32*NBIG + i];
    lat[i] = s;
}

// ---------------- attention ----------------
__global__ void attn_kernel(const float* __restrict__ q, const float* __restrict__ k,
                            const float* __restrict__ v, float* __restrict__ ao) {
    int bh = blockIdx.x;
    int b = bh >> 3, h = bh & 7;
    int s = threadIdx.x;
    __shared__ float ks[64][32];
    __shared__ float vs[64][32];
    for (int idx = s; idx < 2048; idx += 64) {
        int l = idx >> 5, d = idx & 31;
        size_t src = (size_t)(b*64 + l)*DMODEL + h*32 + d;
        ks[l][d] = k[src];
        vs[l][d] = v[src];
    }
    __syncthreads();

    float qr[32];
    const float* qp = q + (size_t)(b*64 + s)*DMODEL + h*32;
    #pragma unroll
    for (int d = 0; d < 32; d++) qr[d] = qp[d];

    // RoPE (bug-faithful)
    #pragma unroll
    for (int i = 0; i < 16; i++) {
        float fr = powf(10000.0f, -(float)i / 16.0f);
        float ang = (float)s * fr;
        float c = cosf(ang), sn = sinf(ang);
        float X = qr[2*i], Y = qr[2*i + 1];
        float nX = X*c - Y*sn;
        float nY = nX*sn + Y*c;
        qr[2*i] = nX; qr[2*i + 1] = nY;
    }

    const float scale = 0.1767766952966369f;
    float sc[64];
    float mx = -1e30f;
    #pragma unroll
    for (int l = 0; l < 64; l++) {
        float p = 0.f;
        #pragma unroll
        for (int d = 0; d < 32; d++) p += qr[d] * ks[l][d];
        p *= scale;
        sc[l] = p;
        mx = fmaxf(mx, p);
    }
    float se = 0.f;
    #pragma unroll
    for (int l = 0; l < 64; l++) { sc[l] = __expf(sc[l] - mx); se += sc[l]; }
    float inv = 1.0f / se;

    float* op = ao + (size_t)(b*64 + s)*DMODEL + h*32;
    #pragma unroll
    for (int d = 0; d < 32; d++) {
        float a = 0.f;
        #pragma unroll
        for (int l = 0; l < 64; l++) a += sc[l] * vs[l][d];
        op[d] = a * inv;
    }
}

// ---------------- router ----------------
__global__ void zero_cnt_kernel(int* cnt) { if (threadIdx.x < NEXP) cnt[threadIdx.x] = 0; }

__global__ void route_kernel(const float* __restrict__ y2, const float* __restrict__ rw,
                             const float* __restrict__ rb, float* __restrict__ topv,
                             int* __restrict__ cnt, int* __restrict__ list) {
    int tok = blockIdx.x, lane = threadIdx.x;
    float xv[8];
    #pragma unroll
    for (int j = 0; j < 8; j++) xv[j] = y2[(size_t)tok*DMODEL + j*32 + lane];
    float lg[8];
    #pragma unroll
    for (int e = 0; e < 8; e++) {
        float p = 0.f;
        #pragma unroll
        for (int j = 0; j < 8; j++) p += xv[j] * rw[(j*32 + lane)*NEXP + e];
        #pragma unroll
        for (int o = 16; o > 0; o >>= 1) p += __shfl_xor_sync(0xffffffffu, p, o);
        lg[e] = p;
    }
    if (lane == 0) {
        float mx = -1e30f;
        #pragma unroll
        for (int e = 0; e < 8; e++) { lg[e] += rb[e]; mx = fmaxf(mx, lg[e]); }
        float se = 0.f, pr[8];
        #pragma unroll
        for (int e = 0; e < 8; e++) { pr[e] = __expf(lg[e] - mx); se += pr[e]; }
        float inv = 1.0f / se;
        #pragma unroll
        for (int e = 0; e < 8; e++) pr[e] *= inv;
        int b0 = 0; float v0 = -1.f;
        #pragma unroll
        for (int e = 0; e < 8; e++) if (pr[e] > v0) { v0 = pr[e]; b0 = e; }
        int b1 = -1; float v1 = -1.f;
        #pragma unroll
        for (int e = 0; e < 8; e++) if (e != b0 && pr[e] > v1) { v1 = pr[e]; b1 = e; }
        topv[tok*2 + 0] = v0;
        topv[tok*2 + 1] = v1;
        int p0 = atomicAdd(&cnt[b0], 1); list[b0*TOK + p0] = tok*2;
        int p1 = atomicAdd(&cnt[b1], 1); list[b1*TOK + p1] = tok*2 + 1;
    }
}

// ---------------- combine ----------------
__global__ void combine_kernel(const float* __restrict__ x2, const float* __restrict__ topv,
                               const float* __restrict__ eo, float* __restrict__ out) {
    int tok = blockIdx.x, d = threadIdx.x;
    size_t i = (size_t)tok*DMODEL + d;
    out[i] = x2[i] + topv[tok*2] * eo[i] + topv[tok*2 + 1] * eo[(size_t)TOK*DMODEL + i];
}

// ---------------- host ----------------
extern "C" void kernel_launch(void* const* d_in, const int* in_sizes, int n_in,
                              void* d_out, int out_size) {
    const float* x   = (const float*)d_in[0];
    const float* r1w = (const float*)d_in[1];
    const float* Wl  = (const float*)d_in[2];
    const float* bl  = (const float*)d_in[3];
    const float* Wq  = (const float*)d_in[4];
    const float* bq  = (const float*)d_in[5];
    const float* Wk  = (const float*)d_in[6];
    const float* bk  = (const float*)d_in[7];
    const float* Wv  = (const float*)d_in[8];
    const float* bv  = (const float*)d_in[9];
    const float* Wo  = (const float*)d_in[10];
    const float* bo  = (const float*)d_in[11];
    const float* r2w = (const float*)d_in[12];
    const float* rw  = (const float*)d_in[13];
    const float* rb  = (const float*)d_in[14];
    const float* W1  = (const float*)d_in[15];
    const float* b1  = (const float*)d_in[16];
    const float* Wsx = (const float*)d_in[17];
    const float* bs  = (const float*)d_in[18];
    const float* W2  = (const float*)d_in[19];
    const float* b2  = (const float*)d_in[20];

    float *y1, *part, *lat, *qkv, *ao, *x2, *y2, *topv, *eo;
    __half *w116, *ws16, *w216, *wq16, *wk16, *wv16, *wo16, *h1x, *h2x;
    int *cnt, *list;
    cudaGetSymbolAddress((void**)&y1,   g_y1);
    cudaGetSymbolAddress((void**)&part, g_part);
    cudaGetSymbolAddress((void**)&lat,  g_lat);
    cudaGetSymbolAddress((void**)&qkv,  g_qkv);
    cudaGetSymbolAddress((void**)&ao,   g_ao);
    cudaGetSymbolAddress((void**)&x2,   g_x2);
    cudaGetSymbolAddress((void**)&y2,   g_y2);
    cudaGetSymbolAddress((void**)&topv, g_topv);
    cudaGetSymbolAddress((void**)&cnt,  g_cnt);
    cudaGetSymbolAddress((void**)&list, g_list);
    cudaGetSymbolAddress((void**)&eo,   g_eo);
    cudaGetSymbolAddress((void**)&h1x,  g_h1x);
    cudaGetSymbolAddress((void**)&h2x,  g_h2x);
    cudaGetSymbolAddress((void**)&w116, g_w116);
    cudaGetSymbolAddress((void**)&ws16, g_ws16);
    cudaGetSymbolAddress((void**)&w216, g_w216);
    cudaGetSymbolAddress((void**)&wq16, g_wq16);
    cudaGetSymbolAddress((void**)&wk16, g_wk16);
    cudaGetSymbolAddress((void**)&wv16, g_wv16);
    cudaGetSymbolAddress((void**)&wo16, g_wo16);

    static int smem_set = 0;
    if (!smem_set) {
        cudaFuncSetAttribute(hgemm,      cudaFuncAttributeMaxDynamicSharedMemorySize, SMEM128);
        cudaFuncSetAttribute(hgemm_f16a, cudaFuncAttributeMaxDynamicSharedMemorySize, SMEM128);
        cudaFuncSetAttribute(hgemm_wl,   cudaFuncAttributeMaxDynamicSharedMemorySize, SMEMW);
        smem_set = 1;
    }

    // weight conversions
    cvt_qkvo_w<<<1024, 256>>>(Wq, Wk, Wv, Wo, wq16, wk16, wv16, wo16);
    cvt_moe_w<<<49152, 256>>>(W1, Wsx, W2, w116, ws16, w216);

    // --- MHLA ---
    rmsnorm_kernel<<<TOK, 256>>>(x, r1w, y1);
    hgemm_wl<<<dim3(64, WLSPLIT), 256, SMEMW>>>(y1, Wl, part);
    wl_reduce<<<TOK, 256>>>(part, bl, lat);
    hgemm<<<dim3(2, 16, 3), 256, SMEM128>>>(y1, wq16, bq, nullptr, qkv, nullptr, 0,
        TOK, DMODEL, DMODEL, DMODEL, nullptr, nullptr, 5, 0,
        lat, wk16, wv16, bk, bv);
    attn_kernel<<<256, 64>>>(qkv, qkv + (size_t)TOK*DMODEL, qkv + 2*(size_t)TOK*DMODEL, ao);
    hgemm<<<dim3(2, 16, 1), 256, SMEM128>>>(ao, wo16, bo, x, x2, nullptr, 0,
        TOK, DMODEL, DMODEL, DMODEL, nullptr, nullptr, 0, 0,
        nullptr, nullptr, nullptr, nullptr, nullptr);

    // --- MoE ---
    rmsnorm_kernel<<<TOK, 256>>>(x2, r2w, y2);
    zero_cnt_kernel<<<1, 32>>>(cnt);
    route_kernel<<<TOK, 32>>>(y2, rw, rb, topv, cnt, list);
    hgemm<<<dim3(8, 16, NEXP), 256, SMEM128>>>(y2, w116, b1, nullptr, nullptr, h1x, HPLANE,
        0, FEXP, DMODEL, DMODEL, list, cnt, 1, 0,
        nullptr, nullptr, nullptr, nullptr, nullptr);
    hgemm_f16a<<<dim3(8, 16, NEXP), 256, SMEM128>>>(h1x, HPLANE, ws16, bs,
        nullptr, h2x, HPLANE, FEXP, FEXP, FEXP, list, cnt, 2, 1);
    hgemm_f16a<<<dim3(2, 16, NEXP), 256, SMEM128>>>(h2x, HPLANE, w216, b2,
        eo, nullptr, 0, DMODEL, FEXP, FEXP, list, cnt, 3, 0);
    combine_kernel<<<TOK, 256>>>(x2, topv, eo, (float*)d_out);
}

// round 11
// speedup vs baseline: 1.1804x; 1.0079x over previous
#include <cuda_runtime.h>
#include <cuda_bf16.h>
#include <cuda_fp16.h>

typedef unsigned long long ull;

// B=32, S=64, D=256, H=8, E=8, topk=2, F=1024, LATENT=64, HD=32
#define TOK      2048
#define DMODEL   256
#define NBIG     16384
#define FEXP     1024
#define NEXP     8
#define WLSPLIT  4
#define WLKC     (NBIG/WLSPLIT)   // 4096

// ---------------- scratch ----------------
__device__ float  g_y1 [TOK*DMODEL];
__device__ float  g_part[WLSPLIT*32*NBIG];
__device__ float  g_lat[TOK*DMODEL];
__device__ float  g_qkv[3*TOK*DMODEL];
__device__ float  g_ao [TOK*DMODEL];
__device__ float  g_x2 [TOK*DMODEL];
__device__ float  g_y2 [TOK*DMODEL];
__device__ float  g_topv[TOK*2];
__device__ int    g_cnt[NEXP];
__device__ int    g_list[NEXP*TOK];
__device__ float  g_h1 [NEXP*TOK*FEXP];
__device__ float  g_h2 [NEXP*TOK*FEXP];
__device__ float  g_eo [2*TOK*DMODEL];
__device__ __align__(16) __half g_w116[NEXP*DMODEL*FEXP];
__device__ __align__(16) __half g_ws16[NEXP*FEXP*FEXP];
__device__ __align__(16) __half g_w216[NEXP*FEXP*DMODEL];
__device__ __align__(16) __half g_wq16[DMODEL*DMODEL];
__device__ __align__(16) __half g_wk16[DMODEL*DMODEL];
__device__ __align__(16) __half g_wv16[DMODEL*DMODEL];
__device__ __align__(16) __half g_wo16[DMODEL*DMODEL];

// ---------------- helpers ----------------
__device__ __forceinline__ unsigned smem_u32(const void* p) {
    return (unsigned)__cvta_generic_to_shared(p);
}
#define CPA16(dst, src) asm volatile("cp.async.cg.shared.global [%0], [%1], 16;" :: "r"(dst), "l"(src))
#define CPA_COMMIT()    asm volatile("cp.async.commit_group;")
#define CPA_WAIT0()     asm volatile("cp.async.wait_group 0;")
__device__ __forceinline__ void ldm_x4(unsigned* r, unsigned addr) {
    asm volatile("ldmatrix.sync.aligned.m8n8.x4.shared.b16 {%0,%1,%2,%3}, [%4];"
        : "=r"(r[0]), "=r"(r[1]), "=r"(r[2]), "=r"(r[3]) : "r"(addr));
}
__device__ __forceinline__ void ldm_x4t(unsigned* r, unsigned addr) {
    asm volatile("ldmatrix.sync.aligned.m8n8.x4.trans.shared.b16 {%0,%1,%2,%3}, [%4];"
        : "=r"(r[0]), "=r"(r[1]), "=r"(r[2]), "=r"(r[3]) : "r"(addr));
}
__device__ __forceinline__ void ldm_x2t(unsigned* r, unsigned addr) {
    asm volatile("ldmatrix.sync.aligned.m8n8.x2.trans.shared.b16 {%0,%1}, [%2];"
        : "=r"(r[0]), "=r"(r[1]) : "r"(addr));
}
__device__ __forceinline__ void mma_bf16(float* c, const unsigned* a, const unsigned* b) {
    asm volatile("mma.sync.aligned.m16n8k16.row.col.f32.bf16.bf16.f32 "
        "{%0,%1,%2,%3}, {%4,%5,%6,%7}, {%8,%9}, {%0,%1,%2,%3};"
        : "+f"(c[0]), "+f"(c[1]), "+f"(c[2]), "+f"(c[3])
        : "r"(a[0]), "r"(a[1]), "r"(a[2]), "r"(a[3]), "r"(b[0]), "r"(b[1]));
}
__device__ __forceinline__ void mma_f16(float* c, const unsigned* a, const unsigned* b) {
    asm volatile("mma.sync.aligned.m16n8k16.row.col.f32.f16.f16.f32 "
        "{%0,%1,%2,%3}, {%4,%5,%6,%7}, {%8,%9}, {%0,%1,%2,%3};"
        : "+f"(c[0]), "+f"(c[1]), "+f"(c[2]), "+f"(c[3])
        : "r"(a[0]), "r"(a[1]), "r"(a[2]), "r"(a[3]), "r"(b[0]), "r"(b[1]));
}
// bf16 split (Wl kernel)
__device__ __forceinline__ void split_pair(float x, float y, unsigned& hi, unsigned& lo) {
    unsigned ux = __float_as_uint(x), uy = __float_as_uint(y);
    hi = __byte_perm(ux, uy, 0x7632);
    float lx = x - __uint_as_float(ux & 0xFFFF0000u);
    float ly = y - __uint_as_float(uy & 0xFFFF0000u);
    asm("cvt.rn.bf16x2.f32 %0, %1, %2;" : "=r"(lo) : "f"(ly), "f"(lx));
}
// fp16 pack / split
__device__ __forceinline__ unsigned pack_f16(float x, float y) {
    unsigned r;
    asm("cvt.rn.f16x2.f32 %0, %1, %2;" : "=r"(r) : "f"(y), "f"(x));
    return r;
}
__device__ __forceinline__ void split_pair_f16(float x, float y, unsigned& hi, unsigned& lo) {
    hi = pack_f16(x, y);
    __half2 h = *reinterpret_cast<__half2*>(&hi);
    float2 hf = __half22float2(h);
    lo = pack_f16(x - hf.x, y - hf.y);
}

// ================= hgemm: BM=128 BN=128 BK=32, fp32 A (2-pass split) + fp16 W ====
// mode 0: C[r]=A[r]@W+bias(+resid)   mode 1: A gathered via list>>1 -> C at e*TOK
// mode 2: A at e*TOK -> C at e*TOK (+relu)   mode 3: A at e*TOK -> C scattered
// mode 5: fused QKV (z selects A/W/bias), C slice z*TOK*N
#define A128_STRIDE 40      // f16 elems (80 B)
#define B128_STRIDE 136     // f16 elems (272 B)
#define AH128 0
#define AL128 10240
#define BH128 20480
#define BUF128 29184        // AH + AL + BH(8704)
#define ROWP128 (2*BUF128)
#define SMEM128 (2*BUF128 + 1024 + 256)

extern "C" __global__ void __launch_bounds__(256)
hgemm(const float* __restrict__ A, const __half* __restrict__ W16,
      const float* __restrict__ bias, const float* __restrict__ resid,
      float* __restrict__ C, int M, int N, int K, int lda,
      const int* __restrict__ list, const int* __restrict__ cntp,
      int mode, int relu,
      const float* A2, const __half* Wk16, const __half* Wv16,
      const float* bk2, const float* bv3) {
    extern __shared__ char sm_raw[];
    char* sm = (char*)(((ull)sm_raw + 127) & ~127ULL);

    int z = blockIdx.z;
    int e = (mode >= 1 && mode <= 3) ? z : 0;
    const float* Asrc = A;
    const __half* Wsrc = W16;
    const float* bsrc = bias;
    if (mode == 5 && z > 0) {
        Asrc = A2;
        Wsrc = (z == 1) ? Wk16 : Wv16;
        bsrc = (z == 1) ? bk2 : bv3;
    }
    int rows = cntp ? cntp[e] : M;
    int m0 = blockIdx.y * 128;
    if (m0 >= rows) return;
    int n0 = blockIdx.x * 128;
    int tid = threadIdx.x;
    int lane = tid & 31, w = tid >> 5;
    int wm = w & 1, wn = w >> 1;

    const __half* We = Wsrc + (size_t)e * K * N;
    const float* be = bsrc + (size_t)e * N;

    const float** rowp = (const float**)(sm + ROWP128);
    if (tid < 128) {
        int r = m0 + tid;
        const float* p = nullptr;
        if (r < rows) {
            if (mode == 1)      p = Asrc + (size_t)(list[e*TOK + r] >> 1) * lda;
            else if (mode == 2 || mode == 3) p = Asrc + ((size_t)e*TOK + r) * lda;
            else                p = Asrc + (size_t)r * lda;
        }
        rowp[tid] = p;
    }
    __syncthreads();

    unsigned smbase = smem_u32(sm);
    int aq = lane >> 3, ar = lane & 7;
    unsigned a_base = smbase + AH128 +
        (unsigned)(((wm*64 + ar + 8*(aq & 1)) * A128_STRIDE + 8*(aq >> 1)) * 2);
    int bt = lane >> 3;
    int bkrow = (bt & 1)*8 + (lane & 7);
    int bnoff = (bt >> 1)*8;
    unsigned b_base = smbase + BH128 +
        (unsigned)((bkrow * B128_STRIDE + wn*32 + bnoff) * 2);

    float acc[4][4][4];
    #pragma unroll
    for (int i = 0; i < 4; i++)
        #pragma unroll
        for (int j = 0; j < 4; j++)
            #pragma unroll
            for (int q = 0; q < 4; q++) acc[i][j][q] = 0.f;

    int nch = K >> 5;
    float4 av[4];

    // ---- prologue: chunk 0 ----
    {
        unsigned bb = smbase;
        #pragma unroll
        for (int p = 0; p < 2; p++) {
            int s = tid + 256*p;
            CPA16(bb + BH128 + (s >> 4)*272 + (s & 15)*16,
                  (const char*)(We + (size_t)(s >> 4)*N + n0 + (s & 15)*8));
        }
        CPA_COMMIT();
        #pragma unroll
        for (int p = 0; p < 4; p++) {
            int s = tid + 256*p;
            const float* rp = rowp[s >> 3];
            av[p] = rp ? *(const float4*)(rp + (s & 7)*4) : make_float4(0.f,0.f,0.f,0.f);
        }
        char* bc = sm;
        #pragma unroll
        for (int p = 0; p < 4; p++) {
            int s = tid + 256*p;
            int m = s >> 3, kq = s & 7;
            unsigned h0, l0, h1, l1;
            split_pair_f16(av[p].x, av[p].y, h0, l0);
            split_pair_f16(av[p].z, av[p].w, h1, l1);
            unsigned aoff = (unsigned)(m*(A128_STRIDE*2) + kq*8);
            *(uint2*)(bc + AH128 + aoff) = make_uint2(h0, h1);
            *(uint2*)(bc + AL128 + aoff) = make_uint2(l0, l1);
        }
        CPA_WAIT0();
        __syncthreads();
    }

    for (int c = 0; c < nch; c++) {
        int buf = c & 1;
        bool has = (c + 1 < nch);
        if (has) {
            int kc = (c + 1) << 5;
            unsigned bb = smbase + (unsigned)((buf ^ 1) * BUF128);
            #pragma unroll
            for (int p = 0; p < 2; p++) {
                int s = tid + 256*p;
                CPA16(bb + BH128 + (s >> 4)*272 + (s & 15)*16,
                      (const char*)(We + (size_t)(kc + (s >> 4))*N + n0 + (s & 15)*8));
            }
            CPA_COMMIT();
            #pragma unroll
            for (int p = 0; p < 4; p++) {
                int s = tid + 256*p;
                const float* rp = rowp[s >> 3];
                av[p] = rp ? *(const float4*)(rp + kc + (s & 7)*4) : make_float4(0.f,0.f,0.f,0.f);
            }
        }
        // ---- compute on buf ----
        unsigned bufo = (unsigned)(buf * BUF128);
        #pragma unroll
        for (int ks = 0; ks < 2; ks++) {
            unsigned ah[4][4], al[4][4], bf[2][4];
            unsigned ab = a_base + bufo + ks*32;
            unsigned bb2 = b_base + bufo + ks*16*(B128_STRIDE*2);
            #pragma unroll
            for (int i = 0; i < 4; i++) {
                ldm_x4(ah[i], ab + i*16*(A128_STRIDE*2));
                ldm_x4(al[i], ab + i*16*(A128_STRIDE*2) + (AL128 - AH128));
            }
            #pragma unroll
            for (int jj = 0; jj < 2; jj++) ldm_x4t(bf[jj], bb2 + jj*32);
            #pragma unroll
            for (int i = 0; i < 4; i++)
                #pragma unroll
                for (int j = 0; j < 4; j++) {
                    mma_f16(acc[i][j], ah[i], &bf[j >> 1][(j & 1)*2]);
                    mma_f16(acc[i][j], al[i], &bf[j >> 1][(j & 1)*2]);
                }
        }
        if (has) {
            char* bc = sm + (buf ^ 1) * BUF128;
            #pragma unroll
            for (int p = 0; p < 4; p++) {
                int s = tid + 256*p;
                int m = s >> 3, kq = s & 7;
                unsigned h0, l0, h1, l1;
                split_pair_f16(av[p].x, av[p].y, h0, l0);
                split_pair_f16(av[p].z, av[p].w, h1, l1);
                unsigned aoff = (unsigned)(m*(A128_STRIDE*2) + kq*8);
                *(uint2*)(bc + AH128 + aoff) = make_uint2(h0, h1);
                *(uint2*)(bc + AL128 + aoff) = make_uint2(l0, l1);
            }
            CPA_WAIT0();
        }
        __syncthreads();
    }

    // ---- epilogue ----
    #pragma unroll
    for (int i = 0; i < 4; i++) {
        int r0 = m0 + wm*64 + 16*i + (lane >> 2);
        #pragma unroll
        for (int hf = 0; hf < 2; hf++) {
            int row = r0 + hf*8;
            if (row >= rows) continue;
            float* crow;
            const float* rsd = nullptr;
            if (mode == 3) {
                int ent = list[e*TOK + row];
                crow = C + (size_t)(ent & 1)*TOK*N + (size_t)(ent >> 1)*N;
            } else if (mode == 0) {
                crow = C + (size_t)row * N;
                if (resid) rsd = resid + (size_t)row * N;
            } else if (mode == 5) {
                crow = C + (size_t)z*TOK*N + (size_t)row * N;
            } else {      // mode 1 / 2
                crow = C + ((size_t)e*TOK + row) * N;
            }
            #pragma unroll
            for (int j = 0; j < 4; j++) {
                int col = n0 + wn*32 + 8*j + 2*(lane & 3);
                float v0 = acc[i][j][hf*2 + 0];
                float v1 = acc[i][j][hf*2 + 1];
                v0 += be[col]; v1 += be[col + 1];
                if (rsd) { v0 += rsd[col]; v1 += rsd[col + 1]; }
                if (relu) { v0 = fmaxf(v0, 0.f); v1 = fmaxf(v1, 0.f); }
                *(float2*)(crow + col) = make_float2(v0, v1);
            }
        }
    }
}

// ================= hgemm_wl: BM=32 BN=256 BK=32, split-K=4, bf16 3-pass =========
#define AW_STRIDE 40
#define BW_STRIDE 264
#define AHW 0
#define ALW 2560
#define BHW 5120
#define BLW 22016
#define BUFW 38912
#define SMEMW (2*BUFW + 256)

extern "C" __global__ void __launch_bounds__(256)
hgemm_wl(const float* __restrict__ A, const float* __restrict__ W,
         float* __restrict__ part) {
    extern __shared__ char sm_raw[];
    char* sm = (char*)(((ull)sm_raw + 127) & ~127ULL);

    int n0 = blockIdx.x * 256;
    int z  = blockIdx.y;
    int tid = threadIdx.x;
    int lane = tid & 31, w = tid >> 5;

    const float* Ab = A + (size_t)z * WLKC;
    const float* Wb = W + (size_t)z * WLKC * NBIG;

    unsigned smbase = smem_u32(sm);
    int aq = lane >> 3, ar = lane & 7;
    unsigned a_base = smbase + AHW +
        (unsigned)(((ar + 8*(aq & 1)) * AW_STRIDE + 8*(aq >> 1)) * 2);
    unsigned b_base = smbase + BHW +
        (unsigned)(((lane & 15) * BW_STRIDE + w*32) * 2);

    float acc[2][4][4];
    #pragma unroll
    for (int i = 0; i < 2; i++)
        #pragma unroll
        for (int j = 0; j < 4; j++)
            #pragma unroll
            for (int q = 0; q < 4; q++) acc[i][j][q] = 0.f;

    const int nch = WLKC >> 5;   // 128
    float4 av1; float4 bv[8];

    {
        int m = tid >> 3, kq = tid & 7;
        av1 = *(const float4*)(Ab + (size_t)m*NBIG + kq*4);
        #pragma unroll
        for (int p = 0; p < 8; p++) {
            int s = tid + 256*p;
            bv[p] = *(const float4*)(Wb + (size_t)(s >> 6)*NBIG + n0 + (s & 63)*4);
        }
        char* bb = sm;
        unsigned h0, l0, h1, l1;
        split_pair(av1.x, av1.y, h0, l0);
        split_pair(av1.z, av1.w, h1, l1);
        unsigned aoff = (unsigned)(m*(AW_STRIDE*2) + kq*8);
        *(uint2*)(bb + AHW + aoff) = make_uint2(h0, h1);
        *(uint2*)(bb + ALW + aoff) = make_uint2(l0, l1);
        #pragma unroll
        for (int p = 0; p < 8; p++) {
            int s = tid + 256*p;
            int n4 = s & 63, kk = s >> 6;
            split_pair(bv[p].x, bv[p].y, h0, l0);
            split_pair(bv[p].z, bv[p].w, h1, l1);
            unsigned boff = (unsigned)(kk*(BW_STRIDE*2) + n4*8);
            *(uint2*)(bb + BHW + boff) = make_uint2(h0, h1);
            *(uint2*)(bb + BLW + boff) = make_uint2(l0, l1);
        }
    }
    __syncthreads();

    for (int c = 0; c < nch; c++) {
        int buf = c & 1;
        bool has = (c + 1 < nch);
        if (has) {
            int kc = (c + 1) << 5;
            int m = tid >> 3, kq = tid & 7;
            av1 = *(const float4*)(Ab + (size_t)m*NBIG + kc + kq*4);
            #pragma unroll
            for (int p = 0; p < 8; p++) {
                int s = tid + 256*p;
                bv[p] = *(const float4*)(Wb + (size_t)(kc + (s >> 6))*NBIG + n0 + (s & 63)*4);
            }
        }
        unsigned bufo = (unsigned)(buf * BUFW);
        #pragma unroll
        for (int ks = 0; ks < 2; ks++) {
            unsigned ah[2][4], al[2][4], bh[4][2], bl[4][2];
            unsigned ab = a_base + bufo + ks*32;
            unsigned bb2 = b_base + bufo + ks*16*(BW_STRIDE*2);
            #pragma unroll
            for (int i = 0; i < 2; i++) {
                ldm_x4(ah[i], ab + i*16*(AW_STRIDE*2));
                ldm_x4(al[i], ab + i*16*(AW_STRIDE*2) + (ALW - AHW));
            }
            #pragma unroll
            for (int j = 0; j < 4; j++) {
                ldm_x2t(bh[j], bb2 + j*16);
                ldm_x2t(bl[j], bb2 + j*16 + (BLW - BHW));
            }
            #pragma unroll
            for (int i = 0; i < 2; i++)
                #pragma unroll
                for (int j = 0; j < 4; j++) {
                    mma_bf16(acc[i][j], ah[i], bh[j]);
                    mma_bf16(acc[i][j], al[i], bh[j]);
                    mma_bf16(acc[i][j], ah[i], bl[j]);
                }
        }
        if (has) {
            char* bb = sm + (buf ^ 1) * BUFW;
            int m = tid >> 3, kq = tid & 7;
            unsigned h0, l0, h1, l1;
            split_pair(av1.x, av1.y, h0, l0);
            split_pair(av1.z, av1.w, h1, l1);
            unsigned aoff = (unsigned)(m*(AW_STRIDE*2) + kq*8);
            *(uint2*)(bb + AHW + aoff) = make_uint2(h0, h1);
            *(uint2*)(bb + ALW + aoff) = make_uint2(l0, l1);
            #pragma unroll
            for (int p = 0; p < 8; p++) {
                int s = tid + 256*p;
                int n4 = s & 63, kk = s >> 6;
                split_pair(bv[p].x, bv[p].y, h0, l0);
                split_pair(bv[p].z, bv[p].w, h1, l1);
                unsigned boff = (unsigned)(kk*(BW_STRIDE*2) + n4*8);
                *(uint2*)(bb + BHW + boff) = make_uint2(h0, h1);
                *(uint2*)(bb + BLW + boff) = make_uint2(l0, l1);
            }
        }
        __syncthreads();
    }

    float* pz = part + (size_t)z * 32 * NBIG;
    #pragma unroll
    for (int i = 0; i < 2; i++) {
        int r0 = 16*i + (lane >> 2);
        #pragma unroll
        for (int hf = 0; hf < 2; hf++) {
            int row = r0 + hf*8;
            float* crow = pz + (size_t)row * NBIG;
            #pragma unroll
            for (int j = 0; j < 4; j++) {
                int col = n0 + w*32 + 8*j + 2*(lane & 3);
                *(float2*)(crow + col) =
                    make_float2(acc[i][j][hf*2 + 0], acc[i][j][hf*2 + 1]);
            }
        }
    }
}

// ---------------- weight conversion ----------------
__global__ void cvt_moe_w(const float* __restrict__ W1, const float* __restrict__ Ws,
                          const float* __restrict__ W2, __half* __restrict__ o1,
                          __half* __restrict__ os, __half* __restrict__ o2) {
    size_t i = (size_t)blockIdx.x * 256 + threadIdx.x;
    const size_t n1 = (size_t)NEXP*DMODEL*FEXP;
    const size_t ns = (size_t)NEXP*FEXP*FEXP;
    if (i < n1)            o1[i]        = __float2half_rn(W1[i]);
    else if (i < n1 + ns)  os[i - n1]   = __float2half_rn(Ws[i - n1]);
    else                   o2[i-n1-ns]  = __float2half_rn(W2[i - n1 - ns]);
}
__global__ void cvt_qkvo_w(const float* __restrict__ Wq, const float* __restrict__ Wk,
                           const float* __restrict__ Wv, const float* __restrict__ Wo,
                           __half* __restrict__ oq, __half* __restrict__ ok,
                           __half* __restrict__ ov, __half* __restrict__ oo) {
    size_t i = (size_t)blockIdx.x * 256 + threadIdx.x;
    int seg = (int)(i >> 16);
    size_t j = i & 65535;
    const float* s = (seg == 0) ? Wq : (seg == 1) ? Wk : (seg == 2) ? Wv : Wo;
    __half* d = (seg == 0) ? oq : (seg == 1) ? ok : (seg == 2) ? ov : oo;
    d[j] = __float2half_rn(s[j]);
}

// ---------------- rmsnorm ----------------
__global__ void rmsnorm_kernel(const float* __restrict__ in, const float* __restrict__ w,
                               float* __restrict__ out) {
    int row = blockIdx.x, t = threadIdx.x;
    float v = in[(size_t)row*DMODEL + t];
    float ss = v*v;
    #pragma unroll
    for (int o = 16; o > 0; o >>= 1) ss += __shfl_xor_sync(0xffffffffu, ss, o);
    __shared__ float ws[8];
    if ((t & 31) == 0) ws[t >> 5] = ss;
    __syncthreads();
    float tot = 0.f;
    #pragma unroll
    for (int i = 0; i < 8; i++) tot += ws[i];
    float sc = rsqrtf(tot * (1.0f/256.0f) + 1e-5f);
    out[(size_t)row*DMODEL + t] = v * sc * w[t];
}

// ---------------- Wl split-K reduce ----------------
__global__ void wl_reduce(const float* __restrict__ part, const float* __restrict__ bl,
                          float* __restrict__ lat) {
    int i = blockIdx.x * 256 + threadIdx.x;
    float s = bl[i & (NBIG-1)];
    #pragma unroll
    for (int p = 0; p < WLSPLIT; p++) s += part[(size_t)p*32*NBIG + i];
    lat[i] = s;
}

// ---------------- attention ----------------
__global__ void attn_kernel(const float* __restrict__ q, const float* __restrict__ k,
                            const float* __restrict__ v, float* __restrict__ ao) {
    int bh = blockIdx.x;
    int b = bh >> 3, h = bh & 7;
    int s = threadIdx.x;
    __shared__ float ks[64][32];
    __shared__ float vs[64][32];
    for (int idx = s; idx < 2048; idx += 64) {
        int l = idx >> 5, d = idx & 31;
        size_t src = (size_t)(b*64 + l)*DMODEL + h*32 + d;
        ks[l][d] = k[src];
        vs[l][d] = v[src];
    }
    __syncthreads();

    float qr[32];
    const float* qp = q + (size_t)(b*64 + s)*DMODEL + h*32;
    #pragma unroll
    for (int d = 0; d < 32; d++) qr[d] = qp[d];

    // RoPE (bug-faithful)
    #pragma unroll
    for (int i = 0; i < 16; i++) {
        float fr = powf(10000.0f, -(float)i / 16.0f);
        float ang = (float)s * fr;
        float c = cosf(ang), sn = sinf(ang);
        float X = qr[2*i], Y = qr[2*i + 1];
        float nX = X*c - Y*sn;
        float nY = nX*sn + Y*c;
        qr[2*i] = nX; qr[2*i + 1] = nY;
    }

    const float scale = 0.1767766952966369f;
    float sc[64];
    float mx = -1e30f;
    #pragma unroll
    for (int l = 0; l < 64; l++) {
        float p = 0.f;
        #pragma unroll
        for (int d = 0; d < 32; d++) p += qr[d] * ks[l][d];
        p *= scale;
        sc[l] = p;
        mx = fmaxf(mx, p);
    }
    float se = 0.f;
    #pragma unroll
    for (int l = 0; l < 64; l++) { sc[l] = __expf(sc[l] - mx); se += sc[l]; }
    float inv = 1.0f / se;

    float* op = ao + (size_t)(b*64 + s)*DMODEL + h*32;
    #pragma unroll
    for (int d = 0; d < 32; d++) {
        float a = 0.f;
        #pragma unroll
        for (int l = 0; l < 64; l++) a += sc[l] * vs[l][d];
        op[d] = a * inv;
    }
}

// ---------------- router ----------------
__global__ void zero_cnt_kernel(int* cnt) { if (threadIdx.x < NEXP) cnt[threadIdx.x] = 0; }

__global__ void route_kernel(const float* __restrict__ y2, const float* __restrict__ rw,
                             const float* __restrict__ rb, float* __restrict__ topv,
                             int* __restrict__ cnt, int* __restrict__ list) {
    int tok = blockIdx.x, lane = threadIdx.x;
    float xv[8];
    #pragma unroll
    for (int j = 0; j < 8; j++) xv[j] = y2[(size_t)tok*DMODEL + j*32 + lane];
    float lg[8];
    #pragma unroll
    for (int e = 0; e < 8; e++) {
        float p = 0.f;
        #pragma unroll
        for (int j = 0; j < 8; j++) p += xv[j] * rw[(j*32 + lane)*NEXP + e];
        #pragma unroll
        for (int o = 16; o > 0; o >>= 1) p += __shfl_xor_sync(0xffffffffu, p, o);
        lg[e] = p;
    }
    if (lane == 0) {
        float mx = -1e30f;
        #pragma unroll
        for (int e = 0; e < 8; e++) { lg[e] += rb[e]; mx = fmaxf(mx, lg[e]); }
        float se = 0.f, pr[8];
        #pragma unroll
        for (int e = 0; e < 8; e++) { pr[e] = __expf(lg[e] - mx); se += pr[e]; }
        float inv = 1.0f / se;
        #pragma unroll
        for (int e = 0; e < 8; e++) pr[e] *= inv;
        int b0 = 0; float v0 = -1.f;
        #pragma unroll
        for (int e = 0; e < 8; e++) if (pr[e] > v0) { v0 = pr[e]; b0 = e; }
        int b1 = -1; float v1 = -1.f;
        #pragma unroll
        for (int e = 0; e < 8; e++) if (e != b0 && pr[e] > v1) { v1 = pr[e]; b1 = e; }
        topv[tok*2 + 0] = v0;
        topv[tok*2 + 1] = v1;
        int p0 = atomicAdd(&cnt[b0], 1); list[b0*TOK + p0] = tok*2;
        int p1 = atomicAdd(&cnt[b1], 1); list[b1*TOK + p1] = tok*2 + 1;
    }
}

// ---------------- combine ----------------
__global__ void combine_kernel(const float* __restrict__ x2, const float* __restrict__ topv,
                               const float* __restrict__ eo, float* __restrict__ out) {
    int tok = blockIdx.x, d = threadIdx.x;
    size_t i = (size_t)tok*DMODEL + d;
    out[i] = x2[i] + topv[tok*2] * eo[i] + topv[tok*2 + 1] * eo[(size_t)TOK*DMODEL + i];
}

// ---------------- host ----------------
extern "C" void kernel_launch(void* const* d_in, const int* in_sizes, int n_in,
                              void* d_out, int out_size) {
    const float* x   = (const float*)d_in[0];
    const float* r1w = (const float*)d_in[1];
    const float* Wl  = (const float*)d_in[2];
    const float* bl  = (const float*)d_in[3];
    const float* Wq  = (const float*)d_in[4];
    const float* bq  = (const float*)d_in[5];
    const float* Wk  = (const float*)d_in[6];
    const float* bk  = (const float*)d_in[7];
    const float* Wv  = (const float*)d_in[8];
    const float* bv  = (const float*)d_in[9];
    const float* Wo  = (const float*)d_in[10];
    const float* bo  = (const float*)d_in[11];
    const float* r2w = (const float*)d_in[12];
    const float* rw  = (const float*)d_in[13];
    const float* rb  = (const float*)d_in[14];
    const float* W1  = (const float*)d_in[15];
    const float* b1  = (const float*)d_in[16];
    const float* Wsx = (const float*)d_in[17];
    const float* bs  = (const float*)d_in[18];
    const float* W2  = (const float*)d_in[19];
    const float* b2  = (const float*)d_in[20];

    float *y1, *part, *lat, *qkv, *ao, *x2, *y2, *topv, *h1, *h2, *eo;
    __half *w116, *ws16, *w216, *wq16, *wk16, *wv16, *wo16;
    int *cnt, *list;
    cudaGetSymbolAddress((void**)&y1,   g_y1);
    cudaGetSymbolAddress((void**)&part, g_part);
    cudaGetSymbolAddress((void**)&lat,  g_lat);
    cudaGetSymbolAddress((void**)&qkv,  g_qkv);
    cudaGetSymbolAddress((void**)&ao,   g_ao);
    cudaGetSymbolAddress((void**)&x2,   g_x2);
    cudaGetSymbolAddress((void**)&y2,   g_y2);
    cudaGetSymbolAddress((void**)&topv, g_topv);
    cudaGetSymbolAddress((void**)&cnt,  g_cnt);
    cudaGetSymbolAddress((void**)&list, g_list);
    cudaGetSymbolAddress((void**)&h1,   g_h1);
    cudaGetSymbolAddress((void**)&h2,   g_h2);
    cudaGetSymbolAddress((void**)&eo,   g_eo);
    cudaGetSymbolAddress((void**)&w116, g_w116);
    cudaGetSymbolAddress((void**)&ws16, g_ws16);
    cudaGetSymbolAddress((void**)&w216, g_w216);
    cudaGetSymbolAddress((void**)&wq16, g_wq16);
    cudaGetSymbolAddress((void**)&wk16, g_wk16);
    cudaGetSymbolAddress((void**)&wv16, g_wv16);
    cudaGetSymbolAddress((void**)&wo16, g_wo16);

    static int smem_set = 0;
    if (!smem_set) {
        cudaFuncSetAttribute(hgemm,    cudaFuncAttributeMaxDynamicSharedMemorySize, SMEM128);
        cudaFuncSetAttribute(hgemm_wl, cudaFuncAttributeMaxDynamicSharedMemorySize, SMEMW);
        smem_set = 1;
    }

    // weight conversions
    cvt_qkvo_w<<<1024, 256>>>(Wq, Wk, Wv, Wo, wq16, wk16, wv16, wo16);
    cvt_moe_w<<<49152, 256>>>(W1, Wsx, W2, w116, ws16, w216);

    // --- MHLA ---
    rmsnorm_kernel<<<TOK, 256>>>(x, r1w, y1);
    hgemm_wl<<<dim3(64, WLSPLIT), 256, SMEMW>>>(y1, Wl, part);
    wl_reduce<<<TOK, 256>>>(part, bl, lat);
    hgemm<<<dim3(2, 16, 3), 256, SMEM128>>>(y1, wq16, bq, nullptr, qkv,
        TOK, DMODEL, DMODEL, DMODEL, nullptr, nullptr, 5, 0,
        lat, wk16, wv16, bk, bv);
    attn_kernel<<<256, 64>>>(qkv, qkv + (size_t)TOK*DMODEL, qkv + 2*(size_t)TOK*DMODEL, ao);
    hgemm<<<dim3(2, 16, 1), 256, SMEM128>>>(ao, wo16, bo, x, x2,
        TOK, DMODEL, DMODEL, DMODEL, nullptr, nullptr, 0, 0,
        nullptr, nullptr, nullptr, nullptr, nullptr);

    // --- MoE ---
    rmsnorm_kernel<<<TOK, 256>>>(x2, r2w, y2);
    zero_cnt_kernel<<<1, 32>>>(cnt);
    route_kernel<<<TOK, 32>>>(y2, rw, rb, topv, cnt, list);
    hgemm<<<dim3(8, 16, NEXP), 256, SMEM128>>>(y2, w116, b1, nullptr, h1,
        0, FEXP, DMODEL, DMODEL, list, cnt, 1, 0,
        nullptr, nullptr, nullptr, nullptr, nullptr);
    hgemm<<<dim3(8, 16, NEXP), 256, SMEM128>>>(h1, ws16, bs, nullptr, h2,
        0, FEXP, FEXP, FEXP, list, cnt, 2, 1,
        nullptr, nullptr, nullptr, nullptr, nullptr);
    hgemm<<<dim3(2, 16, NEXP), 256, SMEM128>>>(h2, w216, b2, nullptr, eo,
        0, DMODEL, FEXP, FEXP, list, cnt, 3, 0,
        nullptr, nullptr, nullptr, nullptr, nullptr);
    combine_kernel<<<TOK, 256>>>(x2, topv, eo, (float*)d_out);
}

// round 12
// speedup vs baseline: 1.3207x; 1.1189x over previous
#include <cuda_runtime.h>
#include <cuda_bf16.h>
#include <cuda_fp16.h>

typedef unsigned long long ull;

// B=32, S=64, D=256, H=8, E=8, topk=2, F=1024, LATENT=64, HD=32
#define TOK      2048
#define DMODEL   256
#define NBIG     16384
#define FEXP     1024
#define NEXP     8
#define WLSPLIT  4
#define WLKC     (NBIG/WLSPLIT)   // 4096

// ---------------- scratch ----------------
__device__ float  g_y1 [TOK*DMODEL];
__device__ float  g_part[WLSPLIT*32*NBIG];
__device__ float  g_lat[TOK*DMODEL];
__device__ float  g_qkv[3*TOK*DMODEL];
__device__ float  g_ao [TOK*DMODEL];
__device__ float  g_x2 [TOK*DMODEL];
__device__ float  g_y2 [TOK*DMODEL];
__device__ float  g_topv[TOK*2];
__device__ int    g_cnt[NEXP];
__device__ int    g_list[NEXP*TOK];
__device__ float  g_h1 [NEXP*TOK*FEXP];
__device__ float  g_h2 [NEXP*TOK*FEXP];
__device__ float  g_eo [2*TOK*DMODEL];

// ---------------- helpers ----------------
__device__ __forceinline__ unsigned smem_u32(const void* p) {
    return (unsigned)__cvta_generic_to_shared(p);
}
__device__ __forceinline__ void ldm_x4(unsigned* r, unsigned addr) {
    asm volatile("ldmatrix.sync.aligned.m8n8.x4.shared.b16 {%0,%1,%2,%3}, [%4];"
        : "=r"(r[0]), "=r"(r[1]), "=r"(r[2]), "=r"(r[3]) : "r"(addr));
}
__device__ __forceinline__ void ldm_x4t(unsigned* r, unsigned addr) {
    asm volatile("ldmatrix.sync.aligned.m8n8.x4.trans.shared.b16 {%0,%1,%2,%3}, [%4];"
        : "=r"(r[0]), "=r"(r[1]), "=r"(r[2]), "=r"(r[3]) : "r"(addr));
}
__device__ __forceinline__ void ldm_x2t(unsigned* r, unsigned addr) {
    asm volatile("ldmatrix.sync.aligned.m8n8.x2.trans.shared.b16 {%0,%1}, [%2];"
        : "=r"(r[0]), "=r"(r[1]) : "r"(addr));
}
__device__ __forceinline__ void mma_f16(float* c, const unsigned* a, const unsigned* b) {
    asm volatile("mma.sync.aligned.m16n8k16.row.col.f32.f16.f16.f32 "
        "{%0,%1,%2,%3}, {%4,%5,%6,%7}, {%8,%9}, {%0,%1,%2,%3};"
        : "+f"(c[0]), "+f"(c[1]), "+f"(c[2]), "+f"(c[3])
        : "r"(a[0]), "r"(a[1]), "r"(a[2]), "r"(a[3]), "r"(b[0]), "r"(b[1]));
}
// fp16 pack (round-to-nearest)
__device__ __forceinline__ unsigned pack_f16(float x, float y) {
    unsigned r;
    asm("cvt.rn.f16x2.f32 %0, %1, %2;" : "=r"(r) : "f"(y), "f"(x));
    return r;
}
// fp16 exact 2-term split of a pair
__device__ __forceinline__ void split_pair_f16(float x, float y, unsigned& hi, unsigned& lo) {
    hi = pack_f16(x, y);
    __half2 h = *reinterpret_cast<__half2*>(&hi);
    float2 hf = __half22float2(h);
    lo = pack_f16(x - hf.x, y - hf.y);
}

// ================= hgemm: BM=128 BN=128 BK=32, 8 warps (2m x 4n), fp16 2-pass ====
// mode 0: C[r]=A[r]@W+bias(+resid)   mode 1: A gathered via list>>1 -> C at e*TOK
// mode 2: A at e*TOK -> C at e*TOK (+relu)   mode 3: A at e*TOK -> C scattered (slot,tok)
// mode 5: fused QKV: z selects {A,W,bias}; C slice z*TOK*N
#define A128_STRIDE 40      // f16 elems (80 B)
#define B128_STRIDE 136     // f16 elems (272 B)
#define AH128 0
#define AL128 10240
#define BH128 20480
#define BUF128 29184        // AH(10240)+AL(10240)+BH(8704)
#define ROWP128 (2*BUF128)  // 58368
#define SMEM128 (2*BUF128 + 1024 + 256)

extern "C" __global__ void __launch_bounds__(256)
hgemm(const float* __restrict__ A, const float* __restrict__ W,
      const float* __restrict__ bias, const float* __restrict__ resid,
      float* __restrict__ C, int M, int N, int K, int lda,
      const int* __restrict__ list, const int* __restrict__ cntp,
      int mode, int relu,
      const float* A2, const float* Wk2, const float* Wv3,
      const float* bk2, const float* bv3) {
    extern __shared__ char sm_raw[];
    char* sm = (char*)(((ull)sm_raw + 127) & ~127ULL);

    int z = blockIdx.z;
    int e = (mode >= 1 && mode <= 3) ? z : 0;
    const float* Asrc = A;
    const float* Wsrc = W;
    const float* bsrc = bias;
    if (mode == 5 && z > 0) {
        Asrc = A2;
        Wsrc = (z == 1) ? Wk2 : Wv3;
        bsrc = (z == 1) ? bk2 : bv3;
    }
    int rows = cntp ? cntp[e] : M;
    int m0 = blockIdx.y * 128;
    if (m0 >= rows) return;
    int n0 = blockIdx.x * 128;
    int tid = threadIdx.x;
    int lane = tid & 31, w = tid >> 5;
    int wm = w & 1, wn = w >> 1;

    const float* We = Wsrc + (size_t)e * K * N;
    const float* be = bsrc + (size_t)e * N;

    const float** rowp = (const float**)(sm + ROWP128);
    if (tid < 128) {
        int r = m0 + tid;
        const float* p = nullptr;
        if (r < rows) {
            if (mode == 1)      p = Asrc + (size_t)(list[e*TOK + r] >> 1) * lda;
            else if (mode == 0 || mode == 5) p = Asrc + (size_t)r * lda;
            else                p = Asrc + ((size_t)e*TOK + r) * lda;
        }
        rowp[tid] = p;
    }
    __syncthreads();

    // ldmatrix address bases
    unsigned smbase = smem_u32(sm);
    int aq = lane >> 3, ar = lane & 7;
    unsigned a_base = smbase + AH128 +
        (unsigned)(((wm*64 + ar + 8*(aq & 1)) * A128_STRIDE + 8*(aq >> 1)) * 2);
    int bt = lane >> 3;
    int bkrow = (bt & 1)*8 + (lane & 7);
    int bnoff = (bt >> 1)*8;
    unsigned b_base = smbase + BH128 +
        (unsigned)((bkrow * B128_STRIDE + wn*32 + bnoff) * 2);

    float acc[4][4][4];
    #pragma unroll
    for (int i = 0; i < 4; i++)
        #pragma unroll
        for (int j = 0; j < 4; j++)
            #pragma unroll
            for (int q = 0; q < 4; q++) acc[i][j][q] = 0.f;

    int nch = K >> 5;
    float4 av[4], bv[4];

    // ---- prologue: stage chunk 0 ----
    #pragma unroll
    for (int p = 0; p < 4; p++) {
        int s = tid + 256*p;
        const float* rp = rowp[s >> 3];
        av[p] = rp ? *(const float4*)(rp + (s & 7)*4) : make_float4(0.f,0.f,0.f,0.f);
        bv[p] = *(const float4*)(We + (size_t)(s >> 5)*N + n0 + (s & 31)*4);
    }
    {
        char* bb = sm;
        #pragma unroll
        for (int p = 0; p < 4; p++) {
            int s = tid + 256*p;
            int m = s >> 3, kq = s & 7;
            unsigned h0, l0, h1, l1;
            split_pair_f16(av[p].x, av[p].y, h0, l0);
            split_pair_f16(av[p].z, av[p].w, h1, l1);
            unsigned aoff = (unsigned)(m*(A128_STRIDE*2) + kq*8);
            *(uint2*)(bb + AH128 + aoff) = make_uint2(h0, h1);
            *(uint2*)(bb + AL128 + aoff) = make_uint2(l0, l1);
            int n4 = s & 31, kk = s >> 5;
            unsigned bh0 = pack_f16(bv[p].x, bv[p].y);
            unsigned bh1 = pack_f16(bv[p].z, bv[p].w);
            unsigned boff = (unsigned)(kk*(B128_STRIDE*2) + n4*8);
            *(uint2*)(bb + BH128 + boff) = make_uint2(bh0, bh1);
        }
    }
    __syncthreads();

    for (int c = 0; c < nch; c++) {
        int buf = c & 1;
        bool has = (c + 1 < nch);
        if (has) {
            int kc = (c + 1) << 5;
            #pragma unroll
            for (int p = 0; p < 4; p++) {
                int s = tid + 256*p;
                const float* rp = rowp[s >> 3];
                av[p] = rp ? *(const float4*)(rp + kc + (s & 7)*4) : make_float4(0.f,0.f,0.f,0.f);
                bv[p] = *(const float4*)(We + (size_t)(kc + (s >> 5))*N + n0 + (s & 31)*4);
            }
        }
        // ---- compute on buf ----
        unsigned bufo = (unsigned)(buf * BUF128);
        #pragma unroll
        for (int ks = 0; ks < 2; ks++) {
            unsigned ah[4][4], al[4][4], bf[2][4];
            unsigned ab = a_base + bufo + ks*32;
            unsigned bb2 = b_base + bufo + ks*16*(B128_STRIDE*2);
            #pragma unroll
            for (int i = 0; i < 4; i++) {
                ldm_x4(ah[i], ab + i*16*(A128_STRIDE*2));
                ldm_x4(al[i], ab + i*16*(A128_STRIDE*2) + (AL128 - AH128));
            }
            #pragma unroll
            for (int jj = 0; jj < 2; jj++) ldm_x4t(bf[jj], bb2 + jj*32);
            #pragma unroll
            for (int i = 0; i < 4; i++)
                #pragma unroll
                for (int j = 0; j < 4; j++) {
                    mma_f16(acc[i][j], ah[i], &bf[j >> 1][(j & 1)*2]);
                    mma_f16(acc[i][j], al[i], &bf[j >> 1][(j & 1)*2]);
                }
        }
        if (has) {
            char* bb = sm + (buf ^ 1) * BUF128;
            #pragma unroll
            for (int p = 0; p < 4; p++) {
                int s = tid + 256*p;
                int m = s >> 3, kq = s & 7;
                unsigned h0, l0, h1, l1;
                split_pair_f16(av[p].x, av[p].y, h0, l0);
                split_pair_f16(av[p].z, av[p].w, h1, l1);
                unsigned aoff = (unsigned)(m*(A128_STRIDE*2) + kq*8);
                *(uint2*)(bb + AH128 + aoff) = make_uint2(h0, h1);
                *(uint2*)(bb + AL128 + aoff) = make_uint2(l0, l1);
                int n4 = s & 31, kk = s >> 5;
                unsigned bh0 = pack_f16(bv[p].x, bv[p].y);
                unsigned bh1 = pack_f16(bv[p].z, bv[p].w);
                unsigned boff = (unsigned)(kk*(B128_STRIDE*2) + n4*8);
                *(uint2*)(bb + BH128 + boff) = make_uint2(bh0, bh1);
            }
        }
        __syncthreads();
    }

    // ---- epilogue ----
    #pragma unroll
    for (int i = 0; i < 4; i++) {
        int r0 = m0 + wm*64 + 16*i + (lane >> 2);
        #pragma unroll
        for (int hf = 0; hf < 2; hf++) {
            int row = r0 + hf*8;
            if (row >= rows) continue;
            float* crow;
            const float* rsd = nullptr;
            if (mode == 3) {
                int ent = list[e*TOK + row];
                crow = C + (size_t)(ent & 1)*TOK*N + (size_t)(ent >> 1)*N;
            } else if (mode == 0) {
                crow = C + (size_t)row * N;
                if (resid) rsd = resid + (size_t)row * N;
            } else if (mode == 5) {
                crow = C + (size_t)z*TOK*N + (size_t)row * N;
            } else {
                crow = C + ((size_t)e*TOK + row) * N;
            }
            #pragma unroll
            for (int j = 0; j < 4; j++) {
                int col = n0 + wn*32 + 8*j + 2*(lane & 3);
                float v0 = acc[i][j][hf*2 + 0];
                float v1 = acc[i][j][hf*2 + 1];
                v0 += be[col]; v1 += be[col + 1];
                if (rsd) { v0 += rsd[col]; v1 += rsd[col + 1]; }
                if (relu) { v0 = fmaxf(v0, 0.f); v1 = fmaxf(v1, 0.f); }
                *(float2*)(crow + col) = make_float2(v0, v1);
            }
        }
    }
}

// ================= hgemm_wl: BM=32 BN=256 BK=32, split-K=4, fp16 2-pass =========
// A exact fp16 hi/lo split; B rounded fp16 (single plane). 32 MMAs/chunk.
#define AW_STRIDE 40
#define BW_STRIDE 264
#define AHW 0
#define ALW 2560
#define BHW 5120
#define BUFW 22016          // 5120 + 16896
#define SMEMW (2*BUFW + 256)

extern "C" __global__ void __launch_bounds__(256)
hgemm_wl(const float* __restrict__ A, const float* __restrict__ W,
         float* __restrict__ part) {
    extern __shared__ char sm_raw[];
    char* sm = (char*)(((ull)sm_raw + 127) & ~127ULL);

    int n0 = blockIdx.x * 256;
    int z  = blockIdx.y;
    int tid = threadIdx.x;
    int lane = tid & 31, w = tid >> 5;

    const float* Ab = A + (size_t)z * WLKC;               // row stride NBIG
    const float* Wb = W + (size_t)z * WLKC * NBIG;        // rows of W

    unsigned smbase = smem_u32(sm);
    int aq = lane >> 3, ar = lane & 7;
    unsigned a_base = smbase + AHW +
        (unsigned)(((ar + 8*(aq & 1)) * AW_STRIDE + 8*(aq >> 1)) * 2);
    unsigned b_base = smbase + BHW +
        (unsigned)(((lane & 15) * BW_STRIDE + w*32) * 2);

    float acc[2][4][4];
    #pragma unroll
    for (int i = 0; i < 2; i++)
        #pragma unroll
        for (int j = 0; j < 4; j++)
            #pragma unroll
            for (int q = 0; q < 4; q++) acc[i][j][q] = 0.f;

    const int nch = WLKC >> 5;   // 128
    float4 av1; float4 bv[8];

    // prologue: chunk 0
    {
        int m = tid >> 3, kq = tid & 7;
        av1 = *(const float4*)(Ab + (size_t)m*NBIG + kq*4);
        #pragma unroll
        for (int p = 0; p < 8; p++) {
            int s = tid + 256*p;
            bv[p] = *(const float4*)(Wb + (size_t)(s >> 6)*NBIG + n0 + (s & 63)*4);
        }
        char* bb = sm;
        unsigned h0, l0, h1, l1;
        split_pair_f16(av1.x, av1.y, h0, l0);
        split_pair_f16(av1.z, av1.w, h1, l1);
        unsigned aoff = (unsigned)(m*(AW_STRIDE*2) + kq*8);
        *(uint2*)(bb + AHW + aoff) = make_uint2(h0, h1);
        *(uint2*)(bb + ALW + aoff) = make_uint2(l0, l1);
        #pragma unroll
        for (int p = 0; p < 8; p++) {
            int s = tid + 256*p;
            int n4 = s & 63, kk = s >> 6;
            unsigned bh0 = pack_f16(bv[p].x, bv[p].y);
            unsigned bh1 = pack_f16(bv[p].z, bv[p].w);
            unsigned boff = (unsigned)(kk*(BW_STRIDE*2) + n4*8);
            *(uint2*)(bb + BHW + boff) = make_uint2(bh0, bh1);
        }
    }
    __syncthreads();

    for (int c = 0; c < nch; c++) {
        int buf = c & 1;
        bool has = (c + 1 < nch);
        if (has) {
            int kc = (c + 1) << 5;
            int m = tid >> 3, kq = tid & 7;
            av1 = *(const float4*)(Ab + (size_t)m*NBIG + kc + kq*4);
            #pragma unroll
            for (int p = 0; p < 8; p++) {
                int s = tid + 256*p;
                bv[p] = *(const float4*)(Wb + (size_t)(kc + (s >> 6))*NBIG + n0 + (s & 63)*4);
            }
        }
        unsigned bufo = (unsigned)(buf * BUFW);
        #pragma unroll
        for (int ks = 0; ks < 2; ks++) {
            unsigned ah[2][4], al[2][4], bh[4][2];
            unsigned ab = a_base + bufo + ks*32;
            unsigned bb2 = b_base + bufo + ks*16*(BW_STRIDE*2);
            #pragma unroll
            for (int i = 0; i < 2; i++) {
                ldm_x4(ah[i], ab + i*16*(AW_STRIDE*2));
                ldm_x4(al[i], ab + i*16*(AW_STRIDE*2) + (ALW - AHW));
            }
            #pragma unroll
            for (int j = 0; j < 4; j++) ldm_x2t(bh[j], bb2 + j*16);
            #pragma unroll
            for (int i = 0; i < 2; i++)
                #pragma unroll
                for (int j = 0; j < 4; j++) {
                    mma_f16(acc[i][j], ah[i], bh[j]);
                    mma_f16(acc[i][j], al[i], bh[j]);
                }
        }
        if (has) {
            char* bb = sm + (buf ^ 1) * BUFW;
            int m = tid >> 3, kq = tid & 7;
            unsigned h0, l0, h1, l1;
            split_pair_f16(av1.x, av1.y, h0, l0);
            split_pair_f16(av1.z, av1.w, h1, l1);
            unsigned aoff = (unsigned)(m*(AW_STRIDE*2) + kq*8);
            *(uint2*)(bb + AHW + aoff) = make_uint2(h0, h1);
            *(uint2*)(bb + ALW + aoff) = make_uint2(l0, l1);
            #pragma unroll
            for (int p = 0; p < 8; p++) {
                int s = tid + 256*p;
                int n4 = s & 63, kk = s >> 6;
                unsigned bh0 = pack_f16(bv[p].x, bv[p].y);
                unsigned bh1 = pack_f16(bv[p].z, bv[p].w);
                unsigned boff = (unsigned)(kk*(BW_STRIDE*2) + n4*8);
                *(uint2*)(bb + BHW + boff) = make_uint2(bh0, bh1);
            }
        }
        __syncthreads();
    }

    // epilogue: part[z][row][n]
    float* pz = part + (size_t)z * 32 * NBIG;
    #pragma unroll
    for (int i = 0; i < 2; i++) {
        int r0 = 16*i + (lane >> 2);
        #pragma unroll
        for (int hf = 0; hf < 2; hf++) {
            int row = r0 + hf*8;
            float* crow = pz + (size_t)row * NBIG;
            #pragma unroll
            for (int j = 0; j < 4; j++) {
                int col = n0 + w*32 + 8*j + 2*(lane & 3);
                *(float2*)(crow + col) =
                    make_float2(acc[i][j][hf*2 + 0], acc[i][j][hf*2 + 1]);
            }
        }
    }
}

// ---------------- rmsnorm ----------------
__global__ void rmsnorm_kernel(const float* __restrict__ in, const float* __restrict__ w,
                               float* __restrict__ out) {
    int row = blockIdx.x, t = threadIdx.x;
    float v = in[(size_t)row*DMODEL + t];
    float ss = v*v;
    #pragma unroll
    for (int o = 16; o > 0; o >>= 1) ss += __shfl_xor_sync(0xffffffffu, ss, o);
    __shared__ float ws[8];
    if ((t & 31) == 0) ws[t >> 5] = ss;
    __syncthreads();
    float tot = 0.f;
    #pragma unroll
    for (int i = 0; i < 8; i++) tot += ws[i];
    float sc = rsqrtf(tot * (1.0f/256.0f) + 1e-5f);
    out[(size_t)row*DMODEL + t] = v * sc * w[t];
}

// ---------------- Wl split-K reduce ----------------
__global__ void wl_reduce(const float* __restrict__ part, const float* __restrict__ bl,
                          float* __restrict__ lat) {
    int i = blockIdx.x * 256 + threadIdx.x;
    float s = bl[i & (NBIG-1)];
    #pragma unroll
    for (int p = 0; p < WLSPLIT; p++) s += part[(size_t)p*32*NBIG + i];
    lat[i] = s;
}

// ---------------- attention ----------------
__global__ void attn_kernel(const float* __restrict__ q, const float* __restrict__ k,
                            const float* __restrict__ v, float* __restrict__ ao) {
    int bh = blockIdx.x;
    int b = bh >> 3, h = bh & 7;
    int s = threadIdx.x;
    __shared__ float ks[64][32];
    __shared__ float vs[64][32];
    for (int idx = s; idx < 2048; idx += 64) {
        int l = idx >> 5, d = idx & 31;
        size_t src = (size_t)(b*64 + l)*DMODEL + h*32 + d;
        ks[l][d] = k[src];
        vs[l][d] = v[src];
    }
    __syncthreads();

    float qr[32];
    const float* qp = q + (size_t)(b*64 + s)*DMODEL + h*32;
    #pragma unroll
    for (int d = 0; d < 32; d++) qr[d] = qp[d];

    // RoPE (bug-faithful: imaginary part uses the updated real part)
    #pragma unroll
    for (int i = 0; i < 16; i++) {
        float fr = powf(10000.0f, -(float)i / 16.0f);
        float ang = (float)s * fr;
        float c = cosf(ang), sn = sinf(ang);
        float X = qr[2*i], Y = qr[2*i + 1];
        float nX = X*c - Y*sn;
        float nY = nX*sn + Y*c;
        qr[2*i] = nX; qr[2*i + 1] = nY;
    }

    const float scale = 0.1767766952966369f;
    float sc[64];
    float mx = -1e30f;
    #pragma unroll
    for (int l = 0; l < 64; l++) {
        float p = 0.f;
        #pragma unroll
        for (int d = 0; d < 32; d++) p += qr[d] * ks[l][d];
        p *= scale;
        sc[l] = p;
        mx = fmaxf(mx, p);
    }
    float se = 0.f;
    #pragma unroll
    for (int l = 0; l < 64; l++) { sc[l] = __expf(sc[l] - mx); se += sc[l]; }
    float inv = 1.0f / se;

    float* op = ao + (size_t)(b*64 + s)*DMODEL + h*32;
    #pragma unroll
    for (int d = 0; d < 32; d++) {
        float a = 0.f;
        #pragma unroll
        for (int l = 0; l < 64; l++) a += sc[l] * vs[l][d];
        op[d] = a * inv;
    }
}

// ---------------- router ----------------
__global__ void zero_cnt_kernel(int* cnt) { if (threadIdx.x < NEXP) cnt[threadIdx.x] = 0; }

__global__ void route_kernel(const float* __restrict__ y2, const float* __restrict__ rw,
                             const float* __restrict__ rb, float* __restrict__ topv,
                             int* __restrict__ cnt, int* __restrict__ list) {
    int tok = blockIdx.x, lane = threadIdx.x;
    float xv[8];
    #pragma unroll
    for (int j = 0; j < 8; j++) xv[j] = y2[(size_t)tok*DMODEL + j*32 + lane];
    float lg[8];
    #pragma unroll
    for (int e = 0; e < 8; e++) {
        float p = 0.f;
        #pragma unroll
        for (int j = 0; j < 8; j++) p += xv[j] * rw[(j*32 + lane)*NEXP + e];
        #pragma unroll
        for (int o = 16; o > 0; o >>= 1) p += __shfl_xor_sync(0xffffffffu, p, o);
        lg[e] = p;
    }
    if (lane == 0) {
        float mx = -1e30f;
        #pragma unroll
        for (int e = 0; e < 8; e++) { lg[e] += rb[e]; mx = fmaxf(mx, lg[e]); }
        float se = 0.f, pr[8];
        #pragma unroll
        for (int e = 0; e < 8; e++) { pr[e] = __expf(lg[e] - mx); se += pr[e]; }
        float inv = 1.0f / se;
        #pragma unroll
        for (int e = 0; e < 8; e++) pr[e] *= inv;
        int b0 = 0; float v0 = -1.f;
        #pragma unroll
        for (int e = 0; e < 8; e++) if (pr[e] > v0) { v0 = pr[e]; b0 = e; }
        int b1 = -1; float v1 = -1.f;
        #pragma unroll
        for (int e = 0; e < 8; e++) if (e != b0 && pr[e] > v1) { v1 = pr[e]; b1 = e; }
        topv[tok*2 + 0] = v0;
        topv[tok*2 + 1] = v1;
        int p0 = atomicAdd(&cnt[b0], 1); list[b0*TOK + p0] = tok*2;
        int p1 = atomicAdd(&cnt[b1], 1); list[b1*TOK + p1] = tok*2 + 1;
    }
}

// ---------------- combine ----------------
__global__ void combine_kernel(const float* __restrict__ x2, const float* __restrict__ topv,
                               const float* __restrict__ eo, float* __restrict__ out) {
    int tok = blockIdx.x, d = threadIdx.x;
    size_t i = (size_t)tok*DMODEL + d;
    out[i] = x2[i] + topv[tok*2] * eo[i] + topv[tok*2 + 1] * eo[(size_t)TOK*DMODEL + i];
}

// ---------------- host ----------------
extern "C" void kernel_launch(void* const* d_in, const int* in_sizes, int n_in,
                              void* d_out, int out_size) {
    const float* x   = (const float*)d_in[0];
    const float* r1w = (const float*)d_in[1];
    const float* Wl  = (const float*)d_in[2];
    const float* bl  = (const float*)d_in[3];
    const float* Wq  = (const float*)d_in[4];
    const float* bq  = (const float*)d_in[5];
    const float* Wk  = (const float*)d_in[6];
    const float* bk  = (const float*)d_in[7];
    const float* Wv  = (const float*)d_in[8];
    const float* bv  = (const float*)d_in[9];
    const float* Wo  = (const float*)d_in[10];
    const float* bo  = (const float*)d_in[11];
    const float* r2w = (const float*)d_in[12];
    const float* rw  = (const float*)d_in[13];
    const float* rb  = (const float*)d_in[14];
    const float* W1  = (const float*)d_in[15];
    const float* b1  = (const float*)d_in[16];
    const float* Wsx = (const float*)d_in[17];
    const float* bs  = (const float*)d_in[18];
    const float* W2  = (const float*)d_in[19];
    const float* b2  = (const float*)d_in[20];

    float *y1, *part, *lat, *qkv, *ao, *x2, *y2, *topv, *h1, *h2, *eo;
    int *cnt, *list;
    cudaGetSymbolAddress((void**)&y1,   g_y1);
    cudaGetSymbolAddress((void**)&part, g_part);
    cudaGetSymbolAddress((void**)&lat,  g_lat);
    cudaGetSymbolAddress((void**)&qkv,  g_qkv);
    cudaGetSymbolAddress((void**)&ao,   g_ao);
    cudaGetSymbolAddress((void**)&x2,   g_x2);
    cudaGetSymbolAddress((void**)&y2,   g_y2);
    cudaGetSymbolAddress((void**)&topv, g_topv);
    cudaGetSymbolAddress((void**)&cnt,  g_cnt);
    cudaGetSymbolAddress((void**)&list, g_list);
    cudaGetSymbolAddress((void**)&h1,   g_h1);
    cudaGetSymbolAddress((void**)&h2,   g_h2);
    cudaGetSymbolAddress((void**)&eo,   g_eo);

    static int smem_set = 0;
    if (!smem_set) {
        cudaFuncSetAttribute(hgemm,    cudaFuncAttributeMaxDynamicSharedMemorySize, SMEM128);
        cudaFuncSetAttribute(hgemm_wl, cudaFuncAttributeMaxDynamicSharedMemorySize, SMEMW);
        smem_set = 1;
    }

    // --- MHLA ---
    rmsnorm_kernel<<<TOK, 256>>>(x, r1w, y1);
    hgemm_wl<<<dim3(64, WLSPLIT), 256, SMEMW>>>(y1, Wl, part);
    wl_reduce<<<TOK, 256>>>(part, bl, lat);
    // fused QKV: z=0 Q(y1,Wq,bq), z=1 K(lat,Wk,bk), z=2 V(lat,Wv,bv)
    hgemm<<<dim3(2, 16, 3), 256, SMEM128>>>(y1, Wq, bq, nullptr, qkv,
        TOK, DMODEL, DMODEL, DMODEL, nullptr, nullptr, 5, 0,
        lat, Wk, Wv, bk, bv);
    attn_kernel<<<256, 64>>>(qkv, qkv + (size_t)TOK*DMODEL, qkv + 2*(size_t)TOK*DMODEL, ao);
    hgemm<<<dim3(2, 16, 1), 256, SMEM128>>>(ao, Wo, bo, x, x2,
        TOK, DMODEL, DMODEL, DMODEL, nullptr, nullptr, 0, 0,
        nullptr, nullptr, nullptr, nullptr, nullptr);

    // --- MoE ---
    rmsnorm_kernel<<<TOK, 256>>>(x2, r2w, y2);
    zero_cnt_kernel<<<1, 32>>>(cnt);
    route_kernel<<<TOK, 32>>>(y2, rw, rb, topv, cnt, list);
    hgemm<<<dim3(8, 16, NEXP), 256, SMEM128>>>(y2, W1,  b1, nullptr, h1,
        0, FEXP,   DMODEL, DMODEL, list, cnt, 1, 0,
        nullptr, nullptr, nullptr, nullptr, nullptr);
    hgemm<<<dim3(8, 16, NEXP), 256, SMEM128>>>(h1, Wsx, bs, nullptr, h2,
        0, FEXP,   FEXP,   FEXP,   list, cnt, 2, 1,
        nullptr, nullptr, nullptr, nullptr, nullptr);
    hgemm<<<dim3(2, 16, NEXP), 256, SMEM128>>>(h2, W2,  b2, nullptr, eo,
        0, DMODEL, FEXP,   FEXP,   list, cnt, 3, 0,
        nullptr, nullptr, nullptr, nullptr, nullptr);
    combine_kernel<<<TOK, 256>>>(x2, topv, eo, (float*)d_out);
}